// round 14
// baseline (speedup 1.0000x reference)
#include <cuda_runtime.h>
#include <cuda_bf16.h>
#include <cstdint>

#define Bq   2
#define Fq   768
#define Lq   8192
#define IWq  3072
#define NFFT 16384
#define Mq   (Bq * Lq)          // 16384
#define HM   8192               // half-size FFT length

// ---------------- scratch (device globals; no allocations) ----------------
__device__ __align__(16) float  g_up[(size_t)Mq * IWq];
__device__ __align__(16) float  g_v [(size_t)Bq * Fq * Lq];   // [b][f][t]
__device__ __align__(16) float  g_x1[(size_t)Bq * Fq * Lq];
__device__ __align__(16) float  g_x2[(size_t)Bq * Fq * Lq];
__device__ __align__(16) float  g_ht[(size_t)2 * Fq * Lq];    // h transposed [o][f][t]
__device__ __align__(16) float4 g_Hm[(size_t)2 * Fq * HM];    // merged (H[k], H[8192-k])
__device__ __align__(16) float2 g_tw8a[32 * 256];             // fft8k pass-1 twiddles (fwd)
__device__ __align__(16) float2 g_tw8b[16 * 16];              // fft8k pass-2 twiddles (fwd)
__device__ __align__(16) float2 g_twu[HM];                    // untangle twist e^{-2pi i k/16384}
__device__ __align__(16) __nv_bfloat16 g_uh [(size_t)Mq * Fq];
__device__ __align__(16) __nv_bfloat16 g_ul [(size_t)Mq * Fq];
__device__ __align__(16) __nv_bfloat16 g_wih[(size_t)Fq * IWq];   // w_in [k][n]
__device__ __align__(16) __nv_bfloat16 g_wil[(size_t)Fq * IWq];
__device__ __align__(16) __nv_bfloat16 g_woh[(size_t)Fq * Fq];    // w_out [k][n]
__device__ __align__(16) __nv_bfloat16 g_wol[(size_t)Fq * Fq];
__device__ __align__(16) __nv_bfloat16 g_vh [(size_t)Bq * Fq * Lq];
__device__ __align__(16) __nv_bfloat16 g_vl [(size_t)Bq * Fq * Lq];

// ---------------- helpers ---------------------------------------------------
__device__ __forceinline__ uint32_t cvta_s(const void* p) {
    return (uint32_t)__cvta_generic_to_shared(p);
}
__device__ __forceinline__ void cp16(uint32_t dst, const void* src) {
    asm volatile("cp.async.cg.shared.global [%0], [%1], 16;\n" :: "r"(dst), "l"(src));
}
__device__ __forceinline__ void cp_commit() { asm volatile("cp.async.commit_group;\n"); }
__device__ __forceinline__ void cp_wait1()  { asm volatile("cp.async.wait_group 1;\n"); }
__device__ __forceinline__ void cp_wait0()  { asm volatile("cp.async.wait_group 0;\n"); }

__device__ __forceinline__ void ldsm_x4(uint32_t& r0, uint32_t& r1, uint32_t& r2, uint32_t& r3, uint32_t a) {
    asm volatile("ldmatrix.sync.aligned.m8n8.x4.shared.b16 {%0,%1,%2,%3}, [%4];\n"
                 : "=r"(r0), "=r"(r1), "=r"(r2), "=r"(r3) : "r"(a));
}
__device__ __forceinline__ void ldsm_x4_t(uint32_t& r0, uint32_t& r1, uint32_t& r2, uint32_t& r3, uint32_t a) {
    asm volatile("ldmatrix.sync.aligned.m8n8.x4.trans.shared.b16 {%0,%1,%2,%3}, [%4];\n"
                 : "=r"(r0), "=r"(r1), "=r"(r2), "=r"(r3) : "r"(a));
}
__device__ __forceinline__ void mma_bf16(float* d, const uint32_t* a, const uint32_t* b) {
    asm volatile("mma.sync.aligned.m16n8k16.row.col.f32.bf16.bf16.f32 "
                 "{%0,%1,%2,%3},{%4,%5,%6,%7},{%8,%9},{%0,%1,%2,%3};\n"
                 : "+f"(d[0]), "+f"(d[1]), "+f"(d[2]), "+f"(d[3])
                 : "r"(a[0]), "r"(a[1]), "r"(a[2]), "r"(a[3]), "r"(b[0]), "r"(b[1]));
}

// ---------------- prep: fused cvt_splits + transpose_h + FFT tables ---------
#define NB_U  ((Mq * Fq) / 256)
#define NB_WI ((Fq * IWq) / 256)
#define NB_WO ((Fq * Fq) / 256)
#define NB_T  (2 * (Fq / 32) * (Lq / 32))
#define NB_TW 65   // 32 (tw8a) + 1 (tw8b) + 32 (twu)

__global__ void __launch_bounds__(256) prep_kernel(const float* __restrict__ u,
                                                   const float* __restrict__ w_in,
                                                   const float* __restrict__ w_out,
                                                   const float* __restrict__ h) {
    __shared__ float tile[32][33];
    const int bid = blockIdx.x, tid = threadIdx.x;
    if (bid < NB_U + NB_WI + NB_WO) {
        const float* s;
        __nv_bfloat16 *hi, *lo;
        int i;
        if (bid < NB_U) {
            s = u; hi = g_uh; lo = g_ul; i = bid * 256 + tid;
        } else if (bid < NB_U + NB_WI) {
            s = w_in; hi = g_wih; lo = g_wil; i = (bid - NB_U) * 256 + tid;
        } else {
            s = w_out; hi = g_woh; lo = g_wol; i = (bid - NB_U - NB_WI) * 256 + tid;
        }
        float x = s[i];
        __nv_bfloat16 hh = __float2bfloat16(x);
        hi[i] = hh;
        lo[i] = __float2bfloat16(x - __bfloat162float(hh));
    } else if (bid < NB_U + NB_WI + NB_WO + NB_T) {
        int fb = bid - (NB_U + NB_WI + NB_WO);
        int o = fb / ((Fq / 32) * (Lq / 32));
        int rem = fb % ((Fq / 32) * (Lq / 32));
        int f0 = (rem % (Fq / 32)) * 32;
        int t0 = (rem / (Fq / 32)) * 32;
        const int tx = tid & 31, ty = tid >> 5;
        for (int r = ty; r < 32; r += 8)
            tile[r][tx] = h[((size_t)o * Lq + t0 + r) * Fq + f0 + tx];
        __syncthreads();
        for (int r = ty; r < 32; r += 8)
            g_ht[((size_t)(o * Fq + f0 + r)) * Lq + t0 + tx] = tile[tx][r];
    } else {
        int tb = bid - (NB_U + NB_WI + NB_WO + NB_T);
        if (tb < 32) {              // tw8a: [k1][t], angle = -2pi k1 t / 8192
            int idx = tb * 256 + tid;
            int k1 = idx >> 8, t = idx & 255;
            float s, c;
            sincosf(-6.2831853071795864769f * (float)(k1 * t) * (1.0f / 8192.0f), &s, &c);
            g_tw8a[idx] = make_float2(c, s);
        } else if (tb == 32) {      // tw8b: [j1][m2], angle = -2pi j1 m2 / 256
            if (tid < 256) {
                int j1 = tid >> 4, m2 = tid & 15;
                float s, c;
                sincosf(-6.2831853071795864769f * (float)(j1 * m2) * (1.0f / 256.0f), &s, &c);
                g_tw8b[tid] = make_float2(c, s);
            }
        } else {                    // twu: e^{-2pi i k / 16384}, k in [0, 8192)
            int k = (tb - 33) * 256 + tid;
            float s, c;
            sincosf(-6.2831853071795864769f * (float)k * (1.0f / 16384.0f), &s, &c);
            g_twu[k] = make_float2(c, s);
        }
    }
}

// ---------------- register FFT machinery ------------------------------------
__device__ __constant__ float W32C[16] = {
    1.0f, 0.9807852804032304f, 0.9238795325112867f, 0.8314696123025452f,
    0.7071067811865476f, 0.5555702330196022f, 0.3826834323650898f, 0.19509032201612825f,
    0.0f, -0.19509032201612825f, -0.3826834323650898f, -0.5555702330196022f,
    -0.7071067811865476f, -0.8314696123025452f, -0.9238795325112867f, -0.9807852804032304f };
__device__ __constant__ float W32S[16] = {
    0.0f, -0.19509032201612825f, -0.3826834323650898f, -0.5555702330196022f,
    -0.7071067811865476f, -0.8314696123025452f, -0.9238795325112867f, -0.9807852804032304f,
    -1.0f, -0.9807852804032304f, -0.9238795325112867f, -0.8314696123025452f,
    -0.7071067811865476f, -0.5555702330196022f, -0.3826834323650898f, -0.19509032201612825f };

#define SWAPC(a, b) { float t_ = xr[a]; xr[a] = xr[b]; xr[b] = t_; \
                      t_ = xi[a]; xi[a] = xi[b]; xi[b] = t_; }

template<int DIR>
__device__ __forceinline__ void fft32r(float* xr, float* xi) {
    SWAPC(1,16)  SWAPC(2,8)   SWAPC(3,24)  SWAPC(5,20)
    SWAPC(6,12)  SWAPC(7,28)  SWAPC(9,18)  SWAPC(11,26)
    SWAPC(13,22) SWAPC(15,30) SWAPC(19,25) SWAPC(23,29)
    #pragma unroll
    for (int s = 1; s <= 5; s++) {
        const int half = 1 << (s - 1);
        #pragma unroll
        for (int k = 0; k < 16; k++) {
            int j  = k & (half - 1);
            int i1 = ((k >> (s - 1)) << s) + j;
            int i2 = i1 + half;
            int w  = j * (32 >> s);
            float cs = W32C[w];
            float sn = (DIR < 0) ? W32S[w] : -W32S[w];
            float tr = xr[i2] * cs - xi[i2] * sn;
            float ti = xr[i2] * sn + xi[i2] * cs;
            xr[i2] = xr[i1] - tr; xi[i2] = xi[i1] - ti;
            xr[i1] += tr;         xi[i1] += ti;
        }
    }
}
template<int DIR>
__device__ __forceinline__ void fft16r(float* xr, float* xi) {
    SWAPC(1,8) SWAPC(2,4) SWAPC(3,12) SWAPC(5,10) SWAPC(7,14) SWAPC(11,13)
    #pragma unroll
    for (int s = 1; s <= 4; s++) {
        const int half = 1 << (s - 1);
        #pragma unroll
        for (int k = 0; k < 8; k++) {
            int j  = k & (half - 1);
            int i1 = ((k >> (s - 1)) << s) + j;
            int i2 = i1 + half;
            int w  = j * (32 >> s);
            float cs = W32C[w];
            float sn = (DIR < 0) ? W32S[w] : -W32S[w];
            float tr = xr[i2] * cs - xi[i2] * sn;
            float ti = xr[i2] * sn + xi[i2] * cs;
            xr[i2] = xr[i1] - tr; xi[i2] = xi[i1] - ti;
            xr[i1] += tr;         xi[i1] += ti;
        }
    }
}
#undef SWAPC

// ---- 16384-pt FFT (512 threads, 32 regs), used by hfft (sincosf twiddles) --
template<int DIR, bool WB>
__device__ __forceinline__ void fft16k(float* RE, float* IM, float* xr, float* xi, int tid) {
    const float TW = (DIR < 0) ? -6.2831853071795864769f : 6.2831853071795864769f;
    fft32r<DIR>(xr, xi);
    {
        const float ang1 = TW * (float)tid * (1.0f / 16384.0f);
        RE[tid] = xr[0]; IM[tid] = xi[0];
        #pragma unroll
        for (int k1 = 1; k1 < 32; k1++) {
            float sn, cs;
            __sincosf(ang1 * (float)k1, &sn, &cs);
            RE[k1 * 528 + tid] = xr[k1] * cs - xi[k1] * sn;
            IM[k1 * 528 + tid] = xr[k1] * sn + xi[k1] * cs;
        }
    }
    __syncthreads();
    {
        int k1 = tid >> 4, m2 = tid & 15;
        #pragma unroll
        for (int m1 = 0; m1 < 32; m1++) {
            xr[m1] = RE[k1 * 528 + m1 * 16 + m2];
            xi[m1] = IM[k1 * 528 + m1 * 16 + m2];
        }
        __syncthreads();
        fft32r<DIR>(xr, xi);
        const float ang2 = TW * (float)m2 * (1.0f / 512.0f);
        int wb = k1 * 17 + m2;
        RE[wb] = xr[0]; IM[wb] = xi[0];
        #pragma unroll
        for (int j1 = 1; j1 < 32; j1++) {
            float sn, cs;
            __sincosf(ang2 * (float)j1, &sn, &cs);
            RE[j1 * 544 + wb] = xr[j1] * cs - xi[j1] * sn;
            IM[j1 * 544 + wb] = xr[j1] * sn + xi[j1] * cs;
        }
    }
    __syncthreads();
    {
        int k1 = tid & 31, j1 = tid >> 5;
        #pragma unroll
        for (int m2 = 0; m2 < 16; m2++) {
            xr[m2]      = RE[j1 * 544 + k1 * 17 + m2];
            xi[m2]      = IM[j1 * 544 + k1 * 17 + m2];
            xr[16 + m2] = RE[(j1 + 16) * 544 + k1 * 17 + m2];
            xi[16 + m2] = IM[(j1 + 16) * 544 + k1 * 17 + m2];
        }
        if (WB) __syncthreads();
        fft16r<DIR>(xr, xi);
        fft16r<DIR>(xr + 16, xi + 16);
        if (WB) {
            #pragma unroll
            for (int j2 = 0; j2 < 16; j2++) {
                RE[k1 + 32 * j1 + 1024 * j2] = xr[j2];
                IM[k1 + 32 * j1 + 1024 * j2] = xi[j2];
                RE[k1 + 32 * (j1 + 16) + 1024 * j2] = xr[16 + j2];
                IM[k1 + 32 * (j1 + 16) + 1024 * j2] = xi[16 + j2];
            }
            __syncthreads();
        }
    }
}
#define FFT_SMEM_FLOATS 17408

// ---- 8192-pt FFT (256 threads, 32 regs), table twiddles (inv = conjugate) --
template<int DIR, bool WB>
__device__ __forceinline__ void fft8k(float* RE, float* IM, float* xr, float* xi, int tid) {
    fft32r<DIR>(xr, xi);
    {
        RE[tid] = xr[0]; IM[tid] = xi[0];
        #pragma unroll
        for (int k1 = 1; k1 < 32; k1++) {
            float2 w = g_tw8a[(k1 << 8) + tid];
            float cs = w.x, sn = (DIR < 0) ? w.y : -w.y;
            RE[k1 * 272 + tid] = xr[k1] * cs - xi[k1] * sn;
            IM[k1 * 272 + tid] = xr[k1] * sn + xi[k1] * cs;
        }
    }
    __syncthreads();
    {
        int k1a = tid >> 4, m2 = tid & 15;
        int k1b = k1a + 16;
        #pragma unroll
        for (int m1 = 0; m1 < 16; m1++) {
            xr[m1]      = RE[k1a * 272 + m1 * 16 + m2];
            xi[m1]      = IM[k1a * 272 + m1 * 16 + m2];
            xr[16 + m1] = RE[k1b * 272 + m1 * 16 + m2];
            xi[16 + m1] = IM[k1b * 272 + m1 * 16 + m2];
        }
        __syncthreads();
        fft16r<DIR>(xr, xi);
        fft16r<DIR>(xr + 16, xi + 16);
        int wba = k1a * 17 + m2, wbb = k1b * 17 + m2;
        RE[wba] = xr[0];  IM[wba] = xi[0];
        RE[wbb] = xr[16]; IM[wbb] = xi[16];
        #pragma unroll
        for (int j1 = 1; j1 < 16; j1++) {
            float2 w = g_tw8b[(j1 << 4) + m2];
            float cs = w.x, sn = (DIR < 0) ? w.y : -w.y;
            RE[j1 * 544 + wba] = xr[j1] * cs - xi[j1] * sn;
            IM[j1 * 544 + wba] = xr[j1] * sn + xi[j1] * cs;
            RE[j1 * 544 + wbb] = xr[16 + j1] * cs - xi[16 + j1] * sn;
            IM[j1 * 544 + wbb] = xr[16 + j1] * sn + xi[16 + j1] * cs;
        }
    }
    __syncthreads();
    {
        int k1 = tid & 31, j1a = tid >> 5, j1b = j1a + 8;
        #pragma unroll
        for (int m2 = 0; m2 < 16; m2++) {
            xr[m2]      = RE[j1a * 544 + k1 * 17 + m2];
            xi[m2]      = IM[j1a * 544 + k1 * 17 + m2];
            xr[16 + m2] = RE[j1b * 544 + k1 * 17 + m2];
            xi[16 + m2] = IM[j1b * 544 + k1 * 17 + m2];
        }
        if (WB) __syncthreads();
        fft16r<DIR>(xr, xi);
        fft16r<DIR>(xr + 16, xi + 16);
        if (WB) {
            #pragma unroll
            for (int j2 = 0; j2 < 16; j2++) {
                RE[k1 + 32 * j1a + 512 * j2] = xr[j2];
                IM[k1 + 32 * j1a + 512 * j2] = xi[j2];
                RE[k1 + 32 * j1b + 512 * j2] = xr[16 + j2];
                IM[k1 + 32 * j1b + 512 * j2] = xi[16 + j2];
            }
            __syncthreads();
        }
    }
}
#define CH_SMEM_FLOATS 8704

// ---------------- K1: up = u @ w_in + b_in (256 thr, 128x128, 3-stage) -----
#define UPA_STG 9216
#define UPB_STG 8704
#define UP_SMEM ((3 * UPA_STG + 3 * UPB_STG) * 2)   // 107520 B

__device__ __forceinline__ void up_loadA(__nv_bfloat16* dst, const __nv_bfloat16* Ap,
                                         int m0, int k0, int tid) {
    #pragma unroll
    for (int it = 0; it < 4; it++) {
        int id = tid + it * 256, r = id >> 3, cu = id & 7;
        cp16(cvta_s(dst + r * 72 + cu * 8), Ap + (size_t)(m0 + r) * Fq + k0 + cu * 8);
    }
}
__device__ __forceinline__ void up_loadB(__nv_bfloat16* dst, const __nv_bfloat16* Bp,
                                         int n0, int k0, int tid) {
    #pragma unroll
    for (int it = 0; it < 4; it++) {
        int id = tid + it * 256, r = id >> 4, cu = id & 15;
        cp16(cvta_s(dst + r * 136 + cu * 8), Bp + (size_t)(k0 + r) * IWq + n0 + cu * 8);
    }
}

__global__ void __launch_bounds__(256) gemm_up_tc(const float* __restrict__ bias) {
    extern __shared__ __align__(16) __nv_bfloat16 smp[];
    __nv_bfloat16* As = smp;
    __nv_bfloat16* Bs = smp + 3 * UPA_STG;
    const int m0 = blockIdx.y * 128, n0 = blockIdx.x * 128;
    const int tid = threadIdx.x, lane = tid & 31, wid = tid >> 5;
    const int wm = wid >> 2, wn = wid & 3;
    float acc[4][4][4] = {};

    const __nv_bfloat16* Aseg[3] = { g_uh, g_ul, g_uh };
    const __nv_bfloat16* Bseg[3] = { g_wih, g_wih, g_wil };

    up_loadA(As, Aseg[0], m0, 0, tid);
    up_loadB(Bs, Bseg[0], n0, 0, tid);
    cp_commit();
    up_loadA(As + UPA_STG, Aseg[0], m0, 64, tid);
    up_loadB(Bs + UPB_STG, Bseg[0], n0, 64, tid);
    cp_commit();

    for (int c = 0; c < 36; c++) {
        if (c < 35) cp_wait1(); else cp_wait0();
        __syncthreads();
        int pf = c + 2;
        if (pf < 36) {
            int sg = pf / 12, kc = pf % 12, sl = pf % 3;
            up_loadA(As + sl * UPA_STG, Aseg[sg], m0, kc * 64, tid);
            up_loadB(Bs + sl * UPB_STG, Bseg[sg], n0, kc * 64, tid);
            cp_commit();
        }
        const __nv_bfloat16* Ab = As + (c % 3) * UPA_STG;
        const __nv_bfloat16* Bb = Bs + (c % 3) * UPB_STG;
        #pragma unroll
        for (int ks = 0; ks < 4; ks++) {
            uint32_t a[4][4], bf[4][2];
            #pragma unroll
            for (int mi = 0; mi < 4; mi++) {
                const __nv_bfloat16* p = Ab + (wm * 64 + mi * 16 + (lane & 15)) * 72
                                            + ks * 16 + (lane >> 4) * 8;
                ldsm_x4(a[mi][0], a[mi][1], a[mi][2], a[mi][3], cvta_s(p));
            }
            #pragma unroll
            for (int pr = 0; pr < 2; pr++) {
                const __nv_bfloat16* p = Bb + (ks * 16 + (lane & 15)) * 136
                                            + wn * 32 + pr * 16 + (lane >> 4) * 8;
                ldsm_x4_t(bf[2*pr][0], bf[2*pr][1], bf[2*pr+1][0], bf[2*pr+1][1], cvta_s(p));
            }
            #pragma unroll
            for (int mi = 0; mi < 4; mi++)
                #pragma unroll
                for (int ni = 0; ni < 4; ni++)
                    mma_bf16(acc[mi][ni], a[mi], bf[ni]);
        }
    }
    #pragma unroll
    for (int mi = 0; mi < 4; mi++)
        #pragma unroll
        for (int ni = 0; ni < 4; ni++) {
            int row = m0 + wm * 64 + mi * 16 + (lane >> 2);
            int col = n0 + wn * 32 + ni * 8 + (lane & 3) * 2;
            float b0 = bias[col], b1 = bias[col + 1];
            *(float2*)&g_up[(size_t)row * IWq + col] =
                make_float2(acc[mi][ni][0] + b0, acc[mi][ni][1] + b1);
            *(float2*)&g_up[(size_t)(row + 8) * IWq + col] =
                make_float2(acc[mi][ni][2] + b0, acc[mi][ni][3] + b1);
        }
}

// ---------------- K2: depthwise conv + split + gate (float4 loads) ---------
__global__ void __launch_bounds__(256) conv_gate(const float* __restrict__ convk,
                                                 const float* __restrict__ convb) {
    __shared__ float s_in[34 * 4 * 32];
    __shared__ float s_out[3][32][33];
    const int f0 = blockIdx.x * 32, t0 = blockIdx.y * 32, b = blockIdx.z;
    const int tid = threadIdx.x, tx = tid & 31, ty = tid >> 5;

    for (int q = tid; q < 136 * 8; q += 256) {
        int row = q >> 3, w = q & 7;
        int tt = row >> 2, c4 = row & 3;
        int t = t0 - 2 + tt;
        float4 v = make_float4(0.f, 0.f, 0.f, 0.f);
        if (t >= 0)
            v = *(const float4*)&g_up[(size_t)(b * Lq + t) * IWq + c4 * Fq + f0 + w * 4];
        *(float4*)&s_in[row * 32 + w * 4] = v;
    }
    float kk[4][3], cb[4];
    #pragma unroll
    for (int c4 = 0; c4 < 4; c4++) {
        int c = c4 * Fq + f0 + tx;
        kk[c4][0] = convk[c]; kk[c4][1] = convk[IWq + c]; kk[c4][2] = convk[2 * IWq + c];
        cb[c4] = convb[c];
    }
    __syncthreads();
    #pragma unroll
    for (int q = 0; q < 4; q++) {
        int ts = ty + 8 * q;
        float o[4];
        #pragma unroll
        for (int c4 = 0; c4 < 4; c4++)
            o[c4] = cb[c4]
                  + kk[c4][2] * s_in[((ts + 2) * 4 + c4) * 32 + tx]
                  + kk[c4][1] * s_in[((ts + 1) * 4 + c4) * 32 + tx]
                  + kk[c4][0] * s_in[((ts    ) * 4 + c4) * 32 + tx];
        s_out[0][tx][ts] = o[3] * o[0];
        s_out[1][tx][ts] = o[1];
        s_out[2][tx][ts] = o[2];
    }
    __syncthreads();
    float* dst[3] = { g_v, g_x1, g_x2 };
    #pragma unroll
    for (int jn = 0; jn < 3; jn++)
        #pragma unroll
        for (int qq = 0; qq < 4; qq++) {
            int fr = ty + 8 * qq;
            dst[jn][(size_t)(b * Fq + f0 + fr) * Lq + t0 + tx] = s_out[jn][fr][tx];
        }
}

// ---------------- K3: packed FFT of h -> merged half-spectra ----------------
__global__ void __launch_bounds__(512) hfft_kernel() {
    extern __shared__ float sm[];
    float* RE = sm;
    float* IM = sm + FFT_SMEM_FLOATS;
    const int f = blockIdx.x, tid = threadIdx.x;
    const float* h0 = g_ht + (size_t)f * Lq;
    const float* h1 = g_ht + (size_t)(Fq + f) * Lq;
    float xr[32], xi[32];
    #pragma unroll
    for (int n1 = 0; n1 < 32; n1++) {
        int p = n1 * 512 + tid;
        xr[n1] = (n1 < 16) ? h0[p] : 0.0f;
        xi[n1] = (n1 < 16) ? h1[p] : 0.0f;
    }
    fft16k<-1, true>(RE, IM, xr, xi, tid);
    float4* Hm0 = g_Hm + (size_t)f * HM;
    float4* Hm1 = g_Hm + (size_t)(Fq + f) * HM;
    for (int k = tid; k < HM; k += 512) {
        int m  = (NFFT - k) & (NFFT - 1);
        int kp = HM - k;              // in [1, 8192]
        int mp = NFFT - kp;           // 8192 + k
        float rk = RE[k],  ik = IM[k],  rm = RE[m],  imm = IM[m];
        float rp = RE[kp], ip = IM[kp], rq = RE[mp], iq = IM[mp];
        Hm0[k] = make_float4(0.5f * (rk + rm), 0.5f * (ik - imm),
                             0.5f * (rp + rq), 0.5f * (ip - iq));
        Hm1[k] = make_float4(0.5f * (ik + imm), 0.5f * (rm - rk),
                             0.5f * (ip + iq), 0.5f * (rq - rp));
    }
}

// ---------------- K4: per-(b, f) chain via 8192-pt real-packed FFT ---------
__global__ void __launch_bounds__(256) chain_kernel(const float* __restrict__ bias) {
    extern __shared__ float sm[];
    float* RE = sm;
    float* IM = sm + CH_SMEM_FLOATS;
    const int idx = blockIdx.x;
    const int b = idx / Fq, f = idx % Fq;
    const int tid = threadIdx.x;
    const size_t base = ((size_t)b * Fq + f) * Lq;
    const float inv = 1.0f / 8192.0f;
    float xr[32], xi[32];

    #pragma unroll 1
    for (int o = 0; o < 2; o++) {
        #pragma unroll
        for (int n1 = 0; n1 < 32; n1++) {
            if (n1 < 16) {
                float2 vv = *(const float2*)&g_v[base + 2 * (n1 * 256 + tid)];
                xr[n1] = vv.x; xi[n1] = vv.y;
            } else { xr[n1] = 0.0f; xi[n1] = 0.0f; }
        }
        __syncthreads();
        fft8k<-1, true>(RE, IM, xr, xi, tid);

        const float4* Hf = g_Hm + ((size_t)o * Fq + f) * HM;
        #pragma unroll
        for (int n1 = 0; n1 < 32; n1++) {
            int k   = n1 * 256 + tid;
            int kks = (8192 - k) & 8191;
            float zr = RE[k],   zi = IM[k];
            float wr = RE[kks], wi = IM[kks];
            float zer = 0.5f * (zr + wr), zei = 0.5f * (zi - wi);
            float zor = 0.5f * (zi + wi), zoi = 0.5f * (wr - zr);
            float2 wt = g_twu[k];
            float cs = wt.x, sn = wt.y;
            float vkr = zer + cs * zor - sn * zoi;
            float vki = zei + cs * zoi + sn * zor;
            float vpr = zer - cs * zor + sn * zoi;
            float vpi = -zei + cs * zoi + sn * zor;
            float4 hm = Hf[k];
            float ykr = vkr * hm.x - vki * hm.y, yki = vkr * hm.y + vki * hm.x;
            float ypr = vpr * hm.z - vpi * hm.w, ypi = vpr * hm.w + vpi * hm.z;
            float er  = 0.5f * (ykr + ypr), ei  = 0.5f * (yki - ypi);
            float ocr = 0.5f * (ykr - ypr), oci = 0.5f * (yki + ypi);
            float orr = cs * ocr + sn * oci;
            float ori = cs * oci - sn * ocr;
            xr[n1] = er - ori;
            xi[n1] = ei + orr;
        }
        __syncthreads();
        fft8k<1, false>(RE, IM, xr, xi, tid);

        const float bo = bias[o * Fq + f];
        const float* X = (o == 0 ? g_x1 : g_x2) + base;
        const int k1 = tid & 31, j1a = tid >> 5;
        if (o == 0) {
            #pragma unroll
            for (int j2 = 0; j2 < 8; j2++) {
                int n  = k1 + 32 * j1a + 512 * j2;
                int n2 = n + 256;
                float2 vo = *(const float2*)&g_v[base + 2 * n];
                float2 xg = *(const float2*)&X[2 * n];
                float2 w;
                w.x = (xr[j2] * inv + vo.x * bo) * xg.x;
                w.y = (xi[j2] * inv + vo.y * bo) * xg.y;
                *(float2*)&g_v[base + 2 * n] = w;
                float2 vo2 = *(const float2*)&g_v[base + 2 * n2];
                float2 xg2 = *(const float2*)&X[2 * n2];
                float2 w2;
                w2.x = (xr[16 + j2] * inv + vo2.x * bo) * xg2.x;
                w2.y = (xi[16 + j2] * inv + vo2.y * bo) * xg2.y;
                *(float2*)&g_v[base + 2 * n2] = w2;
            }
        } else {
            #pragma unroll
            for (int j2 = 0; j2 < 8; j2++) {
                int n  = k1 + 32 * j1a + 512 * j2;
                int n2 = n + 256;
                float2 vo = *(const float2*)&g_v[base + 2 * n];
                float2 xg = *(const float2*)&X[2 * n];
                float y0 = (xr[j2] * inv + vo.x * bo) * xg.x;
                float y1 = (xi[j2] * inv + vo.y * bo) * xg.y;
                __nv_bfloat16 h0 = __float2bfloat16(y0);
                __nv_bfloat16 h1 = __float2bfloat16(y1);
                g_vh[base + 2 * n]     = h0;
                g_vh[base + 2 * n + 1] = h1;
                g_vl[base + 2 * n]     = __float2bfloat16(y0 - __bfloat162float(h0));
                g_vl[base + 2 * n + 1] = __float2bfloat16(y1 - __bfloat162float(h1));
                float2 vo2 = *(const float2*)&g_v[base + 2 * n2];
                float2 xg2 = *(const float2*)&X[2 * n2];
                float y2 = (xr[16 + j2] * inv + vo2.x * bo) * xg2.x;
                float y3 = (xi[16 + j2] * inv + vo2.y * bo) * xg2.y;
                __nv_bfloat16 h2 = __float2bfloat16(y2);
                __nv_bfloat16 h3 = __float2bfloat16(y3);
                g_vh[base + 2 * n2]     = h2;
                g_vh[base + 2 * n2 + 1] = h3;
                g_vl[base + 2 * n2]     = __float2bfloat16(y2 - __bfloat162float(h2));
                g_vl[base + 2 * n2 + 1] = __float2bfloat16(y3 - __bfloat162float(h3));
            }
        }
        __syncthreads();
    }
}

// ---------------- K5: out = v2 @ w_out + b_out (256 thr, 128x128, 3-stage) -
#define OTA_STG 8704
#define OTB_STG 8704
#define OT_SMEM ((3 * OTA_STG + 3 * OTB_STG) * 2)   // 104448 B

__device__ __forceinline__ void out_loadA(__nv_bfloat16* dst, const __nv_bfloat16* Ap,
                                          int t0, int k0, int tid) {
    #pragma unroll
    for (int it = 0; it < 4; it++) {
        int id = tid + it * 256, r = id >> 4, cu = id & 15;
        cp16(cvta_s(dst + r * 136 + cu * 8), Ap + (size_t)(k0 + r) * Lq + t0 + cu * 8);
    }
}
__device__ __forceinline__ void out_loadB(__nv_bfloat16* dst, const __nv_bfloat16* Bp,
                                          int n0, int k0, int tid) {
    #pragma unroll
    for (int it = 0; it < 4; it++) {
        int id = tid + it * 256, r = id >> 4, cu = id & 15;
        cp16(cvta_s(dst + r * 136 + cu * 8), Bp + (size_t)(k0 + r) * Fq + n0 + cu * 8);
    }
}

__global__ void __launch_bounds__(256) gemm_out_tc(const float* __restrict__ bias,
                                                   float* __restrict__ out) {
    extern __shared__ __align__(16) __nv_bfloat16 smp[];
    __nv_bfloat16* As = smp;
    __nv_bfloat16* Bs = smp + 3 * OTA_STG;
    const int m0 = blockIdx.y * 128, n0 = blockIdx.x * 128;
    const int b = m0 / Lq, t0 = m0 % Lq;
    const int tid = threadIdx.x, lane = tid & 31, wid = tid >> 5;
    const int wm = wid >> 2, wn = wid & 3;
    float acc[4][4][4] = {};

    const size_t abase = (size_t)b * Fq * Lq;
    const __nv_bfloat16* Aseg[3] = { g_vh + abase, g_vl + abase, g_vh + abase };
    const __nv_bfloat16* Bseg[3] = { g_woh, g_woh, g_wol };

    out_loadA(As, Aseg[0], t0, 0, tid);
    out_loadB(Bs, Bseg[0], n0, 0, tid);
    cp_commit();
    out_loadA(As + OTA_STG, Aseg[0], t0, 64, tid);
    out_loadB(Bs + OTB_STG, Bseg[0], n0, 64, tid);
    cp_commit();

    for (int c = 0; c < 36; c++) {
        if (c < 35) cp_wait1(); else cp_wait0();
        __syncthreads();
        int pf = c + 2;
        if (pf < 36) {
            int sg = pf / 12, kc = pf % 12, sl = pf % 3;
            out_loadA(As + sl * OTA_STG, Aseg[sg], t0, kc * 64, tid);
            out_loadB(Bs + sl * OTB_STG, Bseg[sg], n0, kc * 64, tid);
            cp_commit();
        }
        const __nv_bfloat16* Ab = As + (c % 3) * OTA_STG;
        const __nv_bfloat16* Bb = Bs + (c % 3) * OTB_STG;
        #pragma unroll
        for (int ks = 0; ks < 4; ks++) {
            uint32_t a[4][4], bf[4][2];
            #pragma unroll
            for (int mi = 0; mi < 4; mi++) {
                int krow = ks * 16 + ((lane >> 4) ? 8 : 0) + (lane & 7);
                int mcol = wm * 64 + mi * 16 + ((lane >> 3) & 1) * 8;
                const __nv_bfloat16* p = Ab + krow * 136 + mcol;
                ldsm_x4_t(a[mi][0], a[mi][1], a[mi][2], a[mi][3], cvta_s(p));
            }
            #pragma unroll
            for (int pr = 0; pr < 2; pr++) {
                const __nv_bfloat16* p = Bb + (ks * 16 + (lane & 15)) * 136
                                            + wn * 32 + pr * 16 + (lane >> 4) * 8;
                ldsm_x4_t(bf[2*pr][0], bf[2*pr][1], bf[2*pr+1][0], bf[2*pr+1][1], cvta_s(p));
            }
            #pragma unroll
            for (int mi = 0; mi < 4; mi++)
                #pragma unroll
                for (int ni = 0; ni < 4; ni++)
                    mma_bf16(acc[mi][ni], a[mi], bf[ni]);
        }
    }
    #pragma unroll
    for (int mi = 0; mi < 4; mi++)
        #pragma unroll
        for (int ni = 0; ni < 4; ni++) {
            int row = m0 + wm * 64 + mi * 16 + (lane >> 2);
            int col = n0 + wn * 32 + ni * 8 + (lane & 3) * 2;
            float b0 = bias[col], b1 = bias[col + 1];
            *(float2*)&out[(size_t)row * Fq + col] =
                make_float2(acc[mi][ni][0] + b0, acc[mi][ni][1] + b1);
            *(float2*)&out[(size_t)(row + 8) * Fq + col] =
                make_float2(acc[mi][ni][2] + b0, acc[mi][ni][3] + b1);
        }
}

// ---------------- launch -----------------------------------------------------
extern "C" void kernel_launch(void* const* d_in, const int* in_sizes, int n_in,
                              void* d_out, int out_size) {
    const float* u      = (const float*)d_in[0];
    const float* h      = (const float*)d_in[1];
    const float* bias   = (const float*)d_in[2];
    const float* w_in   = (const float*)d_in[3];
    const float* b_in   = (const float*)d_in[4];
    const float* conv_k = (const float*)d_in[5];
    const float* conv_b = (const float*)d_in[6];
    const float* w_out  = (const float*)d_in[7];
    const float* b_out  = (const float*)d_in[8];
    float* out = (float*)d_out;

    const int fft_smem = FFT_SMEM_FLOATS * 2 * sizeof(float);   // 139264
    const int ch_smem  = CH_SMEM_FLOATS * 2 * sizeof(float);    // 69632
    cudaFuncSetAttribute(hfft_kernel,  cudaFuncAttributeMaxDynamicSharedMemorySize, fft_smem);
    cudaFuncSetAttribute(chain_kernel, cudaFuncAttributeMaxDynamicSharedMemorySize, ch_smem);
    cudaFuncSetAttribute(gemm_up_tc,   cudaFuncAttributeMaxDynamicSharedMemorySize, UP_SMEM);
    cudaFuncSetAttribute(gemm_out_tc,  cudaFuncAttributeMaxDynamicSharedMemorySize, OT_SMEM);

    prep_kernel<<<NB_U + NB_WI + NB_WO + NB_T + NB_TW, 256>>>(u, w_in, w_out, h);
    hfft_kernel<<<Fq, 512, fft_smem>>>();
    gemm_up_tc<<<dim3(IWq / 128, Mq / 128), 256, UP_SMEM>>>(b_in);
    conv_gate<<<dim3(Fq / 32, Lq / 32, Bq), 256>>>(conv_k, conv_b);
    chain_kernel<<<Bq * Fq, 256, ch_smem>>>(bias);
    gemm_out_tc<<<dim3(Fq / 128, Mq / 128), 256, OT_SMEM>>>(b_out, out);
}

// round 15
// speedup vs baseline: 1.0838x; 1.0838x over previous
#include <cuda_runtime.h>
#include <cuda_bf16.h>
#include <cstdint>

#define Bq   2
#define Fq   768
#define Lq   8192
#define IWq  3072
#define NFFT 16384
#define Mq   (Bq * Lq)          // 16384
#define HSTR 8256               // padded half-spectrum stride (>= 8193)

// ---------------- scratch (device globals; no allocations) ----------------
__device__ __align__(16) float  g_up[(size_t)Mq * IWq];
__device__ __align__(16) float  g_v [(size_t)Bq * Fq * Lq];   // [b][f][t]
__device__ __align__(16) float  g_x1[(size_t)Bq * Fq * Lq];
__device__ __align__(16) float  g_x2[(size_t)Bq * Fq * Lq];
__device__ __align__(16) float  g_ht[(size_t)2 * Fq * Lq];    // h transposed [o][f][t]
__device__ __align__(16) float2 g_H [(size_t)2 * Fq * HSTR];  // half spectra of h
__device__ __align__(16) __nv_bfloat16 g_uh [(size_t)Mq * Fq];
__device__ __align__(16) __nv_bfloat16 g_ul [(size_t)Mq * Fq];
__device__ __align__(16) __nv_bfloat16 g_wih[(size_t)Fq * IWq];   // w_in [k][n]
__device__ __align__(16) __nv_bfloat16 g_wil[(size_t)Fq * IWq];
__device__ __align__(16) __nv_bfloat16 g_woh[(size_t)Fq * Fq];    // w_out [k][n]
__device__ __align__(16) __nv_bfloat16 g_wol[(size_t)Fq * Fq];
__device__ __align__(16) __nv_bfloat16 g_vh [(size_t)Bq * Fq * Lq];
__device__ __align__(16) __nv_bfloat16 g_vl [(size_t)Bq * Fq * Lq];

// ---------------- helpers ---------------------------------------------------
__device__ __forceinline__ uint32_t cvta_s(const void* p) {
    return (uint32_t)__cvta_generic_to_shared(p);
}
__device__ __forceinline__ void cp16(uint32_t dst, const void* src) {
    asm volatile("cp.async.cg.shared.global [%0], [%1], 16;\n" :: "r"(dst), "l"(src));
}
__device__ __forceinline__ void cp_commit() { asm volatile("cp.async.commit_group;\n"); }
__device__ __forceinline__ void cp_wait1()  { asm volatile("cp.async.wait_group 1;\n"); }
__device__ __forceinline__ void cp_wait0()  { asm volatile("cp.async.wait_group 0;\n"); }

__device__ __forceinline__ void ldsm_x4(uint32_t& r0, uint32_t& r1, uint32_t& r2, uint32_t& r3, uint32_t a) {
    asm volatile("ldmatrix.sync.aligned.m8n8.x4.shared.b16 {%0,%1,%2,%3}, [%4];\n"
                 : "=r"(r0), "=r"(r1), "=r"(r2), "=r"(r3) : "r"(a));
}
__device__ __forceinline__ void ldsm_x4_t(uint32_t& r0, uint32_t& r1, uint32_t& r2, uint32_t& r3, uint32_t a) {
    asm volatile("ldmatrix.sync.aligned.m8n8.x4.trans.shared.b16 {%0,%1,%2,%3}, [%4];\n"
                 : "=r"(r0), "=r"(r1), "=r"(r2), "=r"(r3) : "r"(a));
}
__device__ __forceinline__ void mma_bf16(float* d, const uint32_t* a, const uint32_t* b) {
    asm volatile("mma.sync.aligned.m16n8k16.row.col.f32.bf16.bf16.f32 "
                 "{%0,%1,%2,%3},{%4,%5,%6,%7},{%8,%9},{%0,%1,%2,%3};\n"
                 : "+f"(d[0]), "+f"(d[1]), "+f"(d[2]), "+f"(d[3])
                 : "r"(a[0]), "r"(a[1]), "r"(a[2]), "r"(a[3]), "r"(b[0]), "r"(b[1]));
}

// ---------------- prep: fused vectorized cvt_splits + transpose_h ----------
#define NB_U  ((Mq * Fq) / 1024)       // 12288
#define NB_WI ((Fq * IWq) / 1024)      // 2304
#define NB_WO ((Fq * Fq) / 1024)       // 576
#define NB_T  (2 * (Fq / 32) * (Lq / 32))  // 12288

__global__ void __launch_bounds__(256) prep_kernel(const float* __restrict__ u,
                                                   const float* __restrict__ w_in,
                                                   const float* __restrict__ w_out,
                                                   const float* __restrict__ h) {
    __shared__ float tile[32][33];
    const int bid = blockIdx.x, tid = threadIdx.x;
    if (bid < NB_U + NB_WI + NB_WO) {
        const float* s;
        __nv_bfloat16 *hi, *lo;
        int i;
        if (bid < NB_U) {
            s = u; hi = g_uh; lo = g_ul; i = (bid * 256 + tid) * 4;
        } else if (bid < NB_U + NB_WI) {
            s = w_in; hi = g_wih; lo = g_wil; i = ((bid - NB_U) * 256 + tid) * 4;
        } else {
            s = w_out; hi = g_woh; lo = g_wol; i = ((bid - NB_U - NB_WI) * 256 + tid) * 4;
        }
        float4 x = *(const float4*)(s + i);
        __nv_bfloat16 h0 = __float2bfloat16(x.x);
        __nv_bfloat16 h1 = __float2bfloat16(x.y);
        __nv_bfloat16 h2 = __float2bfloat16(x.z);
        __nv_bfloat16 h3 = __float2bfloat16(x.w);
        __nv_bfloat16 l0 = __float2bfloat16(x.x - __bfloat162float(h0));
        __nv_bfloat16 l1 = __float2bfloat16(x.y - __bfloat162float(h1));
        __nv_bfloat16 l2 = __float2bfloat16(x.z - __bfloat162float(h2));
        __nv_bfloat16 l3 = __float2bfloat16(x.w - __bfloat162float(h3));
        __nv_bfloat162 ph0 = __nv_bfloat162(h0, h1), ph1 = __nv_bfloat162(h2, h3);
        __nv_bfloat162 pl0 = __nv_bfloat162(l0, l1), pl1 = __nv_bfloat162(l2, l3);
        uint2 wh, wl;
        wh.x = *(uint32_t*)&ph0; wh.y = *(uint32_t*)&ph1;
        wl.x = *(uint32_t*)&pl0; wl.y = *(uint32_t*)&pl1;
        *(uint2*)(hi + i) = wh;
        *(uint2*)(lo + i) = wl;
    } else {
        int fb = bid - (NB_U + NB_WI + NB_WO);
        int o = fb / ((Fq / 32) * (Lq / 32));
        int rem = fb % ((Fq / 32) * (Lq / 32));
        int f0 = (rem % (Fq / 32)) * 32;
        int t0 = (rem / (Fq / 32)) * 32;
        const int tx = tid & 31, ty = tid >> 5;
        for (int r = ty; r < 32; r += 8)
            tile[r][tx] = h[((size_t)o * Lq + t0 + r) * Fq + f0 + tx];
        __syncthreads();
        for (int r = ty; r < 32; r += 8)
            g_ht[((size_t)(o * Fq + f0 + r)) * Lq + t0 + tx] = tile[tx][r];
    }
}

// ---------------- register FFT machinery ------------------------------------
__device__ __constant__ float W32C[16] = {
    1.0f, 0.9807852804032304f, 0.9238795325112867f, 0.8314696123025452f,
    0.7071067811865476f, 0.5555702330196022f, 0.3826834323650898f, 0.19509032201612825f,
    0.0f, -0.19509032201612825f, -0.3826834323650898f, -0.5555702330196022f,
    -0.7071067811865476f, -0.8314696123025452f, -0.9238795325112867f, -0.9807852804032304f };
__device__ __constant__ float W32S[16] = {
    0.0f, -0.19509032201612825f, -0.3826834323650898f, -0.5555702330196022f,
    -0.7071067811865476f, -0.8314696123025452f, -0.9238795325112867f, -0.9807852804032304f,
    -1.0f, -0.9807852804032304f, -0.9238795325112867f, -0.8314696123025452f,
    -0.7071067811865476f, -0.5555702330196022f, -0.3826834323650898f, -0.19509032201612825f };

#define SWAPC(a, b) { float t_ = xr[a]; xr[a] = xr[b]; xr[b] = t_; \
                      t_ = xi[a]; xi[a] = xi[b]; xi[b] = t_; }

template<int DIR>
__device__ __forceinline__ void fft32r(float* xr, float* xi) {
    SWAPC(1,16)  SWAPC(2,8)   SWAPC(3,24)  SWAPC(5,20)
    SWAPC(6,12)  SWAPC(7,28)  SWAPC(9,18)  SWAPC(11,26)
    SWAPC(13,22) SWAPC(15,30) SWAPC(19,25) SWAPC(23,29)
    #pragma unroll
    for (int s = 1; s <= 5; s++) {
        const int half = 1 << (s - 1);
        #pragma unroll
        for (int k = 0; k < 16; k++) {
            int j  = k & (half - 1);
            int i1 = ((k >> (s - 1)) << s) + j;
            int i2 = i1 + half;
            int w  = j * (32 >> s);
            float cs = W32C[w];
            float sn = (DIR < 0) ? W32S[w] : -W32S[w];
            float tr = xr[i2] * cs - xi[i2] * sn;
            float ti = xr[i2] * sn + xi[i2] * cs;
            xr[i2] = xr[i1] - tr; xi[i2] = xi[i1] - ti;
            xr[i1] += tr;         xi[i1] += ti;
        }
    }
}
template<int DIR>
__device__ __forceinline__ void fft16r(float* xr, float* xi) {
    SWAPC(1,8) SWAPC(2,4) SWAPC(3,12) SWAPC(5,10) SWAPC(7,14) SWAPC(11,13)
    #pragma unroll
    for (int s = 1; s <= 4; s++) {
        const int half = 1 << (s - 1);
        #pragma unroll
        for (int k = 0; k < 8; k++) {
            int j  = k & (half - 1);
            int i1 = ((k >> (s - 1)) << s) + j;
            int i2 = i1 + half;
            int w  = j * (32 >> s);
            float cs = W32C[w];
            float sn = (DIR < 0) ? W32S[w] : -W32S[w];
            float tr = xr[i2] * cs - xi[i2] * sn;
            float ti = xr[i2] * sn + xi[i2] * cs;
            xr[i2] = xr[i1] - tr; xi[i2] = xi[i1] - ti;
            xr[i1] += tr;         xi[i1] += ti;
        }
    }
}
#undef SWAPC

// ---- 16384-pt FFT (512 threads, 32 regs), used by hfft ---------------------
template<int DIR, bool WB>
__device__ __forceinline__ void fft16k(float* RE, float* IM, float* xr, float* xi, int tid) {
    const float TW = (DIR < 0) ? -6.2831853071795864769f : 6.2831853071795864769f;
    fft32r<DIR>(xr, xi);
    {
        const float ang1 = TW * (float)tid * (1.0f / 16384.0f);
        RE[tid] = xr[0]; IM[tid] = xi[0];
        #pragma unroll
        for (int k1 = 1; k1 < 32; k1++) {
            float sn, cs;
            __sincosf(ang1 * (float)k1, &sn, &cs);
            RE[k1 * 528 + tid] = xr[k1] * cs - xi[k1] * sn;
            IM[k1 * 528 + tid] = xr[k1] * sn + xi[k1] * cs;
        }
    }
    __syncthreads();
    {
        int k1 = tid >> 4, m2 = tid & 15;
        #pragma unroll
        for (int m1 = 0; m1 < 32; m1++) {
            xr[m1] = RE[k1 * 528 + m1 * 16 + m2];
            xi[m1] = IM[k1 * 528 + m1 * 16 + m2];
        }
        __syncthreads();
        fft32r<DIR>(xr, xi);
        const float ang2 = TW * (float)m2 * (1.0f / 512.0f);
        int wb = k1 * 17 + m2;
        RE[wb] = xr[0]; IM[wb] = xi[0];
        #pragma unroll
        for (int j1 = 1; j1 < 32; j1++) {
            float sn, cs;
            __sincosf(ang2 * (float)j1, &sn, &cs);
            RE[j1 * 544 + wb] = xr[j1] * cs - xi[j1] * sn;
            IM[j1 * 544 + wb] = xr[j1] * sn + xi[j1] * cs;
        }
    }
    __syncthreads();
    {
        int k1 = tid & 31, j1 = tid >> 5;
        #pragma unroll
        for (int m2 = 0; m2 < 16; m2++) {
            xr[m2]      = RE[j1 * 544 + k1 * 17 + m2];
            xi[m2]      = IM[j1 * 544 + k1 * 17 + m2];
            xr[16 + m2] = RE[(j1 + 16) * 544 + k1 * 17 + m2];
            xi[16 + m2] = IM[(j1 + 16) * 544 + k1 * 17 + m2];
        }
        if (WB) __syncthreads();
        fft16r<DIR>(xr, xi);
        fft16r<DIR>(xr + 16, xi + 16);
        if (WB) {
            #pragma unroll
            for (int j2 = 0; j2 < 16; j2++) {
                RE[k1 + 32 * j1 + 1024 * j2] = xr[j2];
                IM[k1 + 32 * j1 + 1024 * j2] = xi[j2];
                RE[k1 + 32 * (j1 + 16) + 1024 * j2] = xr[16 + j2];
                IM[k1 + 32 * (j1 + 16) + 1024 * j2] = xi[16 + j2];
            }
            __syncthreads();
        }
    }
}
#define FFT_SMEM_FLOATS 17408

// ---- 8192-pt FFT (256 threads, 32 regs): passes 32 x 16 x 16 ---------------
template<int DIR, bool WB>
__device__ __forceinline__ void fft8k(float* RE, float* IM, float* xr, float* xi, int tid) {
    const float TW = (DIR < 0) ? -6.2831853071795864769f : 6.2831853071795864769f;
    fft32r<DIR>(xr, xi);
    {
        const float ang1 = TW * (float)tid * (1.0f / 8192.0f);
        RE[tid] = xr[0]; IM[tid] = xi[0];
        #pragma unroll
        for (int k1 = 1; k1 < 32; k1++) {
            float sn, cs;
            __sincosf(ang1 * (float)k1, &sn, &cs);
            RE[k1 * 272 + tid] = xr[k1] * cs - xi[k1] * sn;
            IM[k1 * 272 + tid] = xr[k1] * sn + xi[k1] * cs;
        }
    }
    __syncthreads();
    {
        int k1a = tid >> 4, m2 = tid & 15;
        int k1b = k1a + 16;
        #pragma unroll
        for (int m1 = 0; m1 < 16; m1++) {
            xr[m1]      = RE[k1a * 272 + m1 * 16 + m2];
            xi[m1]      = IM[k1a * 272 + m1 * 16 + m2];
            xr[16 + m1] = RE[k1b * 272 + m1 * 16 + m2];
            xi[16 + m1] = IM[k1b * 272 + m1 * 16 + m2];
        }
        __syncthreads();
        fft16r<DIR>(xr, xi);
        fft16r<DIR>(xr + 16, xi + 16);
        const float ang2 = TW * (float)m2 * (1.0f / 256.0f);
        int wba = k1a * 17 + m2, wbb = k1b * 17 + m2;
        RE[wba] = xr[0];  IM[wba] = xi[0];
        RE[wbb] = xr[16]; IM[wbb] = xi[16];
        #pragma unroll
        for (int j1 = 1; j1 < 16; j1++) {
            float sn, cs;
            __sincosf(ang2 * (float)j1, &sn, &cs);
            RE[j1 * 544 + wba] = xr[j1] * cs - xi[j1] * sn;
            IM[j1 * 544 + wba] = xr[j1] * sn + xi[j1] * cs;
            RE[j1 * 544 + wbb] = xr[16 + j1] * cs - xi[16 + j1] * sn;
            IM[j1 * 544 + wbb] = xr[16 + j1] * sn + xi[16 + j1] * cs;
        }
    }
    __syncthreads();
    {
        int k1 = tid & 31, j1a = tid >> 5, j1b = j1a + 8;
        #pragma unroll
        for (int m2 = 0; m2 < 16; m2++) {
            xr[m2]      = RE[j1a * 544 + k1 * 17 + m2];
            xi[m2]      = IM[j1a * 544 + k1 * 17 + m2];
            xr[16 + m2] = RE[j1b * 544 + k1 * 17 + m2];
            xi[16 + m2] = IM[j1b * 544 + k1 * 17 + m2];
        }
        if (WB) __syncthreads();
        fft16r<DIR>(xr, xi);
        fft16r<DIR>(xr + 16, xi + 16);
        if (WB) {
            #pragma unroll
            for (int j2 = 0; j2 < 16; j2++) {
                RE[k1 + 32 * j1a + 512 * j2] = xr[j2];
                IM[k1 + 32 * j1a + 512 * j2] = xi[j2];
                RE[k1 + 32 * j1b + 512 * j2] = xr[16 + j2];
                IM[k1 + 32 * j1b + 512 * j2] = xi[16 + j2];
            }
            __syncthreads();
        }
    }
}
#define CH_SMEM_FLOATS 8704

// ---------------- K1: up = u @ w_in + b_in (256 thr, 128x128, 3-stage) -----
#define UPA_STG 9216
#define UPB_STG 8704
#define UP_SMEM ((3 * UPA_STG + 3 * UPB_STG) * 2)   // 107520 B

__device__ __forceinline__ void up_loadA(__nv_bfloat16* dst, const __nv_bfloat16* Ap,
                                         int m0, int k0, int tid) {
    #pragma unroll
    for (int it = 0; it < 4; it++) {
        int id = tid + it * 256, r = id >> 3, cu = id & 7;
        cp16(cvta_s(dst + r * 72 + cu * 8), Ap + (size_t)(m0 + r) * Fq + k0 + cu * 8);
    }
}
__device__ __forceinline__ void up_loadB(__nv_bfloat16* dst, const __nv_bfloat16* Bp,
                                         int n0, int k0, int tid) {
    #pragma unroll
    for (int it = 0; it < 4; it++) {
        int id = tid + it * 256, r = id >> 4, cu = id & 15;
        cp16(cvta_s(dst + r * 136 + cu * 8), Bp + (size_t)(k0 + r) * IWq + n0 + cu * 8);
    }
}

__global__ void __launch_bounds__(256) gemm_up_tc(const float* __restrict__ bias) {
    extern __shared__ __align__(16) __nv_bfloat16 smp[];
    __nv_bfloat16* As = smp;
    __nv_bfloat16* Bs = smp + 3 * UPA_STG;
    const int m0 = blockIdx.y * 128, n0 = blockIdx.x * 128;
    const int tid = threadIdx.x, lane = tid & 31, wid = tid >> 5;
    const int wm = wid >> 2, wn = wid & 3;
    float acc[4][4][4] = {};

    const __nv_bfloat16* Aseg[3] = { g_uh, g_ul, g_uh };
    const __nv_bfloat16* Bseg[3] = { g_wih, g_wih, g_wil };

    up_loadA(As, Aseg[0], m0, 0, tid);
    up_loadB(Bs, Bseg[0], n0, 0, tid);
    cp_commit();
    up_loadA(As + UPA_STG, Aseg[0], m0, 64, tid);
    up_loadB(Bs + UPB_STG, Bseg[0], n0, 64, tid);
    cp_commit();

    for (int c = 0; c < 36; c++) {
        if (c < 35) cp_wait1(); else cp_wait0();
        __syncthreads();
        int pf = c + 2;
        if (pf < 36) {
            int sg = pf / 12, kc = pf % 12, sl = pf % 3;
            up_loadA(As + sl * UPA_STG, Aseg[sg], m0, kc * 64, tid);
            up_loadB(Bs + sl * UPB_STG, Bseg[sg], n0, kc * 64, tid);
            cp_commit();
        }
        const __nv_bfloat16* Ab = As + (c % 3) * UPA_STG;
        const __nv_bfloat16* Bb = Bs + (c % 3) * UPB_STG;
        #pragma unroll
        for (int ks = 0; ks < 4; ks++) {
            uint32_t a[4][4], bf[4][2];
            #pragma unroll
            for (int mi = 0; mi < 4; mi++) {
                const __nv_bfloat16* p = Ab + (wm * 64 + mi * 16 + (lane & 15)) * 72
                                            + ks * 16 + (lane >> 4) * 8;
                ldsm_x4(a[mi][0], a[mi][1], a[mi][2], a[mi][3], cvta_s(p));
            }
            #pragma unroll
            for (int pr = 0; pr < 2; pr++) {
                const __nv_bfloat16* p = Bb + (ks * 16 + (lane & 15)) * 136
                                            + wn * 32 + pr * 16 + (lane >> 4) * 8;
                ldsm_x4_t(bf[2*pr][0], bf[2*pr][1], bf[2*pr+1][0], bf[2*pr+1][1], cvta_s(p));
            }
            #pragma unroll
            for (int mi = 0; mi < 4; mi++)
                #pragma unroll
                for (int ni = 0; ni < 4; ni++)
                    mma_bf16(acc[mi][ni], a[mi], bf[ni]);
        }
    }
    #pragma unroll
    for (int mi = 0; mi < 4; mi++)
        #pragma unroll
        for (int ni = 0; ni < 4; ni++) {
            int row = m0 + wm * 64 + mi * 16 + (lane >> 2);
            int col = n0 + wn * 32 + ni * 8 + (lane & 3) * 2;
            float b0 = bias[col], b1 = bias[col + 1];
            *(float2*)&g_up[(size_t)row * IWq + col] =
                make_float2(acc[mi][ni][0] + b0, acc[mi][ni][1] + b1);
            *(float2*)&g_up[(size_t)(row + 8) * IWq + col] =
                make_float2(acc[mi][ni][2] + b0, acc[mi][ni][3] + b1);
        }
}

// ---------------- K2: depthwise conv + split + gate (float4 loads) ---------
__global__ void __launch_bounds__(256) conv_gate(const float* __restrict__ convk,
                                                 const float* __restrict__ convb) {
    __shared__ float s_in[34 * 4 * 32];
    __shared__ float s_out[3][32][33];
    const int f0 = blockIdx.x * 32, t0 = blockIdx.y * 32, b = blockIdx.z;
    const int tid = threadIdx.x, tx = tid & 31, ty = tid >> 5;

    for (int q = tid; q < 136 * 8; q += 256) {
        int row = q >> 3, w = q & 7;
        int tt = row >> 2, c4 = row & 3;
        int t = t0 - 2 + tt;
        float4 v = make_float4(0.f, 0.f, 0.f, 0.f);
        if (t >= 0)
            v = *(const float4*)&g_up[(size_t)(b * Lq + t) * IWq + c4 * Fq + f0 + w * 4];
        *(float4*)&s_in[row * 32 + w * 4] = v;
    }
    float kk[4][3], cb[4];
    #pragma unroll
    for (int c4 = 0; c4 < 4; c4++) {
        int c = c4 * Fq + f0 + tx;
        kk[c4][0] = convk[c]; kk[c4][1] = convk[IWq + c]; kk[c4][2] = convk[2 * IWq + c];
        cb[c4] = convb[c];
    }
    __syncthreads();
    #pragma unroll
    for (int q = 0; q < 4; q++) {
        int ts = ty + 8 * q;
        float o[4];
        #pragma unroll
        for (int c4 = 0; c4 < 4; c4++)
            o[c4] = cb[c4]
                  + kk[c4][2] * s_in[((ts + 2) * 4 + c4) * 32 + tx]
                  + kk[c4][1] * s_in[((ts + 1) * 4 + c4) * 32 + tx]
                  + kk[c4][0] * s_in[((ts    ) * 4 + c4) * 32 + tx];
        s_out[0][tx][ts] = o[3] * o[0];
        s_out[1][tx][ts] = o[1];
        s_out[2][tx][ts] = o[2];
    }
    __syncthreads();
    float* dst[3] = { g_v, g_x1, g_x2 };
    #pragma unroll
    for (int jn = 0; jn < 3; jn++)
        #pragma unroll
        for (int qq = 0; qq < 4; qq++) {
            int fr = ty + 8 * qq;
            dst[jn][(size_t)(b * Fq + f0 + fr) * Lq + t0 + tx] = s_out[jn][fr][tx];
        }
}

// ---------------- K3: packed FFT of h (order0 + i*order1) ------------------
__global__ void __launch_bounds__(512) hfft_kernel() {
    extern __shared__ float sm[];
    float* RE = sm;
    float* IM = sm + FFT_SMEM_FLOATS;
    const int f = blockIdx.x, tid = threadIdx.x;
    const float* h0 = g_ht + (size_t)f * Lq;
    const float* h1 = g_ht + (size_t)(Fq + f) * Lq;
    float xr[32], xi[32];
    #pragma unroll
    for (int n1 = 0; n1 < 32; n1++) {
        int p = n1 * 512 + tid;
        xr[n1] = (n1 < 16) ? h0[p] : 0.0f;
        xi[n1] = (n1 < 16) ? h1[p] : 0.0f;
    }
    fft16k<-1, true>(RE, IM, xr, xi, tid);
    float2* H0 = g_H + (size_t)f * HSTR;
    float2* H1 = g_H + (size_t)(Fq + f) * HSTR;
    for (int k = tid; k <= NFFT / 2; k += 512) {
        int m = (NFFT - k) & (NFFT - 1);
        float rk = RE[k], ik = IM[k], rm = RE[m], imm = IM[m];
        H0[k] = make_float2(0.5f * (rk + rm), 0.5f * (ik - imm));
        H1[k] = make_float2(0.5f * (ik + imm), 0.5f * (rm - rk));
    }
}

// ---------------- K4: per-(b, f) chain via 8192-pt real-packed FFT ---------
__global__ void __launch_bounds__(256) chain_kernel(const float* __restrict__ bias) {
    extern __shared__ float sm[];
    float* RE = sm;
    float* IM = sm + CH_SMEM_FLOATS;
    const int idx = blockIdx.x;           // b * Fq + f
    const int b = idx / Fq, f = idx % Fq;
    const int tid = threadIdx.x;
    const size_t base = ((size_t)b * Fq + f) * Lq;
    const float inv = 1.0f / 8192.0f;
    float xr[32], xi[32];

    #pragma unroll 1
    for (int o = 0; o < 2; o++) {
        #pragma unroll
        for (int n1 = 0; n1 < 32; n1++) {
            if (n1 < 16) {
                float2 vv = *(const float2*)&g_v[base + 2 * (n1 * 256 + tid)];
                xr[n1] = vv.x; xi[n1] = vv.y;
            } else { xr[n1] = 0.0f; xi[n1] = 0.0f; }
        }
        __syncthreads();
        fft8k<-1, true>(RE, IM, xr, xi, tid);

        const float2* Hf = g_H + ((size_t)o * Fq + f) * HSTR;
        #pragma unroll
        for (int n1 = 0; n1 < 32; n1++) {
            int k   = n1 * 256 + tid;
            int kks = (8192 - k) & 8191;
            int kp  = 8192 - k;
            float zr = RE[k],   zi = IM[k];
            float wr = RE[kks], wi = IM[kks];
            float zer = 0.5f * (zr + wr), zei = 0.5f * (zi - wi);
            float zor = 0.5f * (zi + wi), zoi = 0.5f * (wr - zr);
            float sn, cs;
            __sincosf(-6.2831853071795864769f * (float)k * (1.0f / 16384.0f), &sn, &cs);
            float vkr = zer + cs * zor - sn * zoi;
            float vki = zei + cs * zoi + sn * zor;
            float vpr = zer - cs * zor + sn * zoi;
            float vpi = -zei + cs * zoi + sn * zor;
            float2 hk = Hf[k], hp = Hf[kp];
            float ykr = vkr * hk.x - vki * hk.y, yki = vkr * hk.y + vki * hk.x;
            float ypr = vpr * hp.x - vpi * hp.y, ypi = vpr * hp.y + vpi * hp.x;
            float er  = 0.5f * (ykr + ypr), ei  = 0.5f * (yki - ypi);
            float ocr = 0.5f * (ykr - ypr), oci = 0.5f * (yki + ypi);
            float orr = cs * ocr + sn * oci;
            float ori = cs * oci - sn * ocr;
            xr[n1] = er - ori;
            xi[n1] = ei + orr;
        }
        __syncthreads();
        fft8k<1, false>(RE, IM, xr, xi, tid);

        const float bo = bias[o * Fq + f];
        const float* X = (o == 0 ? g_x1 : g_x2) + base;
        const int k1 = tid & 31, j1a = tid >> 5;
        if (o == 0) {
            #pragma unroll
            for (int j2 = 0; j2 < 8; j2++) {
                int n  = k1 + 32 * j1a + 512 * j2;
                int n2 = n + 256;
                float2 vo = *(const float2*)&g_v[base + 2 * n];
                float2 xg = *(const float2*)&X[2 * n];
                float2 w;
                w.x = (xr[j2] * inv + vo.x * bo) * xg.x;
                w.y = (xi[j2] * inv + vo.y * bo) * xg.y;
                *(float2*)&g_v[base + 2 * n] = w;
                float2 vo2 = *(const float2*)&g_v[base + 2 * n2];
                float2 xg2 = *(const float2*)&X[2 * n2];
                float2 w2;
                w2.x = (xr[16 + j2] * inv + vo2.x * bo) * xg2.x;
                w2.y = (xi[16 + j2] * inv + vo2.y * bo) * xg2.y;
                *(float2*)&g_v[base + 2 * n2] = w2;
            }
        } else {
            #pragma unroll
            for (int j2 = 0; j2 < 8; j2++) {
                int n  = k1 + 32 * j1a + 512 * j2;
                int n2 = n + 256;
                float2 vo = *(const float2*)&g_v[base + 2 * n];
                float2 xg = *(const float2*)&X[2 * n];
                float y0 = (xr[j2] * inv + vo.x * bo) * xg.x;
                float y1 = (xi[j2] * inv + vo.y * bo) * xg.y;
                __nv_bfloat16 h0 = __float2bfloat16(y0);
                __nv_bfloat16 h1 = __float2bfloat16(y1);
                g_vh[base + 2 * n]     = h0;
                g_vh[base + 2 * n + 1] = h1;
                g_vl[base + 2 * n]     = __float2bfloat16(y0 - __bfloat162float(h0));
                g_vl[base + 2 * n + 1] = __float2bfloat16(y1 - __bfloat162float(h1));
                float2 vo2 = *(const float2*)&g_v[base + 2 * n2];
                float2 xg2 = *(const float2*)&X[2 * n2];
                float y2 = (xr[16 + j2] * inv + vo2.x * bo) * xg2.x;
                float y3 = (xi[16 + j2] * inv + vo2.y * bo) * xg2.y;
                __nv_bfloat16 h2 = __float2bfloat16(y2);
                __nv_bfloat16 h3 = __float2bfloat16(y3);
                g_vh[base + 2 * n2]     = h2;
                g_vh[base + 2 * n2 + 1] = h3;
                g_vl[base + 2 * n2]     = __float2bfloat16(y2 - __bfloat162float(h2));
                g_vl[base + 2 * n2 + 1] = __float2bfloat16(y3 - __bfloat162float(h3));
            }
        }
        __syncthreads();
    }
}

// ---------------- K5: out = v2 @ w_out + b_out (256 thr, 128x128, 3-stage) -
#define OTA_STG 8704
#define OTB_STG 8704
#define OT_SMEM ((3 * OTA_STG + 3 * OTB_STG) * 2)   // 104448 B

__device__ __forceinline__ void out_loadA(__nv_bfloat16* dst, const __nv_bfloat16* Ap,
                                          int t0, int k0, int tid) {
    #pragma unroll
    for (int it = 0; it < 4; it++) {
        int id = tid + it * 256, r = id >> 4, cu = id & 15;
        cp16(cvta_s(dst + r * 136 + cu * 8), Ap + (size_t)(k0 + r) * Lq + t0 + cu * 8);
    }
}
__device__ __forceinline__ void out_loadB(__nv_bfloat16* dst, const __nv_bfloat16* Bp,
                                          int n0, int k0, int tid) {
    #pragma unroll
    for (int it = 0; it < 4; it++) {
        int id = tid + it * 256, r = id >> 4, cu = id & 15;
        cp16(cvta_s(dst + r * 136 + cu * 8), Bp + (size_t)(k0 + r) * Fq + n0 + cu * 8);
    }
}

__global__ void __launch_bounds__(256) gemm_out_tc(const float* __restrict__ bias,
                                                   float* __restrict__ out) {
    extern __shared__ __align__(16) __nv_bfloat16 smp[];
    __nv_bfloat16* As = smp;
    __nv_bfloat16* Bs = smp + 3 * OTA_STG;
    const int m0 = blockIdx.y * 128, n0 = blockIdx.x * 128;
    const int b = m0 / Lq, t0 = m0 % Lq;
    const int tid = threadIdx.x, lane = tid & 31, wid = tid >> 5;
    const int wm = wid >> 2, wn = wid & 3;
    float acc[4][4][4] = {};

    const size_t abase = (size_t)b * Fq * Lq;
    const __nv_bfloat16* Aseg[3] = { g_vh + abase, g_vl + abase, g_vh + abase };
    const __nv_bfloat16* Bseg[3] = { g_woh, g_woh, g_wol };

    out_loadA(As, Aseg[0], t0, 0, tid);
    out_loadB(Bs, Bseg[0], n0, 0, tid);
    cp_commit();
    out_loadA(As + OTA_STG, Aseg[0], t0, 64, tid);
    out_loadB(Bs + OTB_STG, Bseg[0], n0, 64, tid);
    cp_commit();

    for (int c = 0; c < 36; c++) {
        if (c < 35) cp_wait1(); else cp_wait0();
        __syncthreads();
        int pf = c + 2;
        if (pf < 36) {
            int sg = pf / 12, kc = pf % 12, sl = pf % 3;
            out_loadA(As + sl * OTA_STG, Aseg[sg], t0, kc * 64, tid);
            out_loadB(Bs + sl * OTB_STG, Bseg[sg], n0, kc * 64, tid);
            cp_commit();
        }
        const __nv_bfloat16* Ab = As + (c % 3) * OTA_STG;
        const __nv_bfloat16* Bb = Bs + (c % 3) * OTB_STG;
        #pragma unroll
        for (int ks = 0; ks < 4; ks++) {
            uint32_t a[4][4], bf[4][2];
            #pragma unroll
            for (int mi = 0; mi < 4; mi++) {
                int krow = ks * 16 + ((lane >> 4) ? 8 : 0) + (lane & 7);
                int mcol = wm * 64 + mi * 16 + ((lane >> 3) & 1) * 8;
                const __nv_bfloat16* p = Ab + krow * 136 + mcol;
                ldsm_x4_t(a[mi][0], a[mi][1], a[mi][2], a[mi][3], cvta_s(p));
            }
            #pragma unroll
            for (int pr = 0; pr < 2; pr++) {
                const __nv_bfloat16* p = Bb + (ks * 16 + (lane & 15)) * 136
                                            + wn * 32 + pr * 16 + (lane >> 4) * 8;
                ldsm_x4_t(bf[2*pr][0], bf[2*pr][1], bf[2*pr+1][0], bf[2*pr+1][1], cvta_s(p));
            }
            #pragma unroll
            for (int mi = 0; mi < 4; mi++)
                #pragma unroll
                for (int ni = 0; ni < 4; ni++)
                    mma_bf16(acc[mi][ni], a[mi], bf[ni]);
        }
    }
    #pragma unroll
    for (int mi = 0; mi < 4; mi++)
        #pragma unroll
        for (int ni = 0; ni < 4; ni++) {
            int row = m0 + wm * 64 + mi * 16 + (lane >> 2);
            int col = n0 + wn * 32 + ni * 8 + (lane & 3) * 2;
            float b0 = bias[col], b1 = bias[col + 1];
            *(float2*)&out[(size_t)row * Fq + col] =
                make_float2(acc[mi][ni][0] + b0, acc[mi][ni][1] + b1);
            *(float2*)&out[(size_t)(row + 8) * Fq + col] =
                make_float2(acc[mi][ni][2] + b0, acc[mi][ni][3] + b1);
        }
}

// ---------------- launch -----------------------------------------------------
extern "C" void kernel_launch(void* const* d_in, const int* in_sizes, int n_in,
                              void* d_out, int out_size) {
    const float* u      = (const float*)d_in[0];
    const float* h      = (const float*)d_in[1];
    const float* bias   = (const float*)d_in[2];
    const float* w_in   = (const float*)d_in[3];
    const float* b_in   = (const float*)d_in[4];
    const float* conv_k = (const float*)d_in[5];
    const float* conv_b = (const float*)d_in[6];
    const float* w_out  = (const float*)d_in[7];
    const float* b_out  = (const float*)d_in[8];
    float* out = (float*)d_out;

    const int fft_smem = FFT_SMEM_FLOATS * 2 * sizeof(float);   // 139264
    const int ch_smem  = CH_SMEM_FLOATS * 2 * sizeof(float);    // 69632
    cudaFuncSetAttribute(hfft_kernel,  cudaFuncAttributeMaxDynamicSharedMemorySize, fft_smem);
    cudaFuncSetAttribute(chain_kernel, cudaFuncAttributeMaxDynamicSharedMemorySize, ch_smem);
    cudaFuncSetAttribute(gemm_up_tc,   cudaFuncAttributeMaxDynamicSharedMemorySize, UP_SMEM);
    cudaFuncSetAttribute(gemm_out_tc,  cudaFuncAttributeMaxDynamicSharedMemorySize, OT_SMEM);

    prep_kernel<<<NB_U + NB_WI + NB_WO + NB_T, 256>>>(u, w_in, w_out, h);
    hfft_kernel<<<Fq, 512, fft_smem>>>();
    gemm_up_tc<<<dim3(IWq / 128, Mq / 128), 256, UP_SMEM>>>(b_in);
    conv_gate<<<dim3(Fq / 32, Lq / 32, Bq), 256>>>(conv_k, conv_b);
    chain_kernel<<<Bq * Fq, 256, ch_smem>>>(bias);
    gemm_out_tc<<<dim3(Fq / 128, Mq / 128), 256, OT_SMEM>>>(b_out, out);
}

// round 16
// speedup vs baseline: 1.1393x; 1.0512x over previous
#include <cuda_runtime.h>
#include <cuda_bf16.h>
#include <cstdint>

#define Bq   2
#define Fq   768
#define Lq   8192
#define IWq  3072
#define NFFT 16384
#define Mq   (Bq * Lq)          // 16384
#define HSTR 8256               // padded half-spectrum stride (>= 8193)

// ---------------- scratch (device globals; no allocations) ----------------
__device__ __align__(16) float  g_up[(size_t)Mq * IWq];
__device__ __align__(16) float  g_v [(size_t)Bq * Fq * Lq];   // [b][f][t]
__device__ __align__(16) float  g_x1[(size_t)Bq * Fq * Lq];
__device__ __align__(16) float  g_x2[(size_t)Bq * Fq * Lq];
__device__ __align__(16) float  g_ht[(size_t)2 * Fq * Lq];    // h transposed [o][f][t]
__device__ __align__(16) float2 g_H [(size_t)2 * Fq * HSTR];  // half spectra of h
__device__ __align__(16) __nv_bfloat16 g_uh [(size_t)Mq * Fq];
__device__ __align__(16) __nv_bfloat16 g_ul [(size_t)Mq * Fq];
__device__ __align__(16) __nv_bfloat16 g_wih[(size_t)Fq * IWq];   // w_in [k][n]
__device__ __align__(16) __nv_bfloat16 g_wil[(size_t)Fq * IWq];
__device__ __align__(16) __nv_bfloat16 g_woh[(size_t)Fq * Fq];    // w_out [k][n]
__device__ __align__(16) __nv_bfloat16 g_wol[(size_t)Fq * Fq];
__device__ __align__(16) __nv_bfloat16 g_vh [(size_t)Bq * Fq * Lq];
__device__ __align__(16) __nv_bfloat16 g_vl [(size_t)Bq * Fq * Lq];

// ---------------- helpers ---------------------------------------------------
__device__ __forceinline__ uint32_t cvta_s(const void* p) {
    return (uint32_t)__cvta_generic_to_shared(p);
}
__device__ __forceinline__ void cp16(uint32_t dst, const void* src) {
    asm volatile("cp.async.cg.shared.global [%0], [%1], 16;\n" :: "r"(dst), "l"(src));
}
__device__ __forceinline__ void cp_commit() { asm volatile("cp.async.commit_group;\n"); }
__device__ __forceinline__ void cp_wait1()  { asm volatile("cp.async.wait_group 1;\n"); }
__device__ __forceinline__ void cp_wait0()  { asm volatile("cp.async.wait_group 0;\n"); }

__device__ __forceinline__ void ldsm_x4(uint32_t& r0, uint32_t& r1, uint32_t& r2, uint32_t& r3, uint32_t a) {
    asm volatile("ldmatrix.sync.aligned.m8n8.x4.shared.b16 {%0,%1,%2,%3}, [%4];\n"
                 : "=r"(r0), "=r"(r1), "=r"(r2), "=r"(r3) : "r"(a));
}
__device__ __forceinline__ void ldsm_x4_t(uint32_t& r0, uint32_t& r1, uint32_t& r2, uint32_t& r3, uint32_t a) {
    asm volatile("ldmatrix.sync.aligned.m8n8.x4.trans.shared.b16 {%0,%1,%2,%3}, [%4];\n"
                 : "=r"(r0), "=r"(r1), "=r"(r2), "=r"(r3) : "r"(a));
}
__device__ __forceinline__ void mma_bf16(float* d, const uint32_t* a, const uint32_t* b) {
    asm volatile("mma.sync.aligned.m16n8k16.row.col.f32.bf16.bf16.f32 "
                 "{%0,%1,%2,%3},{%4,%5,%6,%7},{%8,%9},{%0,%1,%2,%3};\n"
                 : "+f"(d[0]), "+f"(d[1]), "+f"(d[2]), "+f"(d[3])
                 : "r"(a[0]), "r"(a[1]), "r"(a[2]), "r"(a[3]), "r"(b[0]), "r"(b[1]));
}

// ---------------- prep: fused vectorized cvt_splits + transpose_h ----------
#define NB_U  ((Mq * Fq) / 1024)       // 12288
#define NB_WI ((Fq * IWq) / 1024)      // 2304
#define NB_WO ((Fq * Fq) / 1024)       // 576
#define NB_T  (2 * (Fq / 32) * (Lq / 32))  // 12288

__global__ void __launch_bounds__(256) prep_kernel(const float* __restrict__ u,
                                                   const float* __restrict__ w_in,
                                                   const float* __restrict__ w_out,
                                                   const float* __restrict__ h) {
    __shared__ float tile[32][33];
    const int bid = blockIdx.x, tid = threadIdx.x;
    if (bid < NB_U + NB_WI + NB_WO) {
        const float* s;
        __nv_bfloat16 *hi, *lo;
        int i;
        if (bid < NB_U) {
            s = u; hi = g_uh; lo = g_ul; i = (bid * 256 + tid) * 4;
        } else if (bid < NB_U + NB_WI) {
            s = w_in; hi = g_wih; lo = g_wil; i = ((bid - NB_U) * 256 + tid) * 4;
        } else {
            s = w_out; hi = g_woh; lo = g_wol; i = ((bid - NB_U - NB_WI) * 256 + tid) * 4;
        }
        float4 x = *(const float4*)(s + i);
        __nv_bfloat16 h0 = __float2bfloat16(x.x);
        __nv_bfloat16 h1 = __float2bfloat16(x.y);
        __nv_bfloat16 h2 = __float2bfloat16(x.z);
        __nv_bfloat16 h3 = __float2bfloat16(x.w);
        __nv_bfloat16 l0 = __float2bfloat16(x.x - __bfloat162float(h0));
        __nv_bfloat16 l1 = __float2bfloat16(x.y - __bfloat162float(h1));
        __nv_bfloat16 l2 = __float2bfloat16(x.z - __bfloat162float(h2));
        __nv_bfloat16 l3 = __float2bfloat16(x.w - __bfloat162float(h3));
        __nv_bfloat162 ph0 = __nv_bfloat162(h0, h1), ph1 = __nv_bfloat162(h2, h3);
        __nv_bfloat162 pl0 = __nv_bfloat162(l0, l1), pl1 = __nv_bfloat162(l2, l3);
        uint2 wh, wl;
        wh.x = *(uint32_t*)&ph0; wh.y = *(uint32_t*)&ph1;
        wl.x = *(uint32_t*)&pl0; wl.y = *(uint32_t*)&pl1;
        *(uint2*)(hi + i) = wh;
        *(uint2*)(lo + i) = wl;
    } else {
        int fb = bid - (NB_U + NB_WI + NB_WO);
        int o = fb / ((Fq / 32) * (Lq / 32));
        int rem = fb % ((Fq / 32) * (Lq / 32));
        int f0 = (rem % (Fq / 32)) * 32;
        int t0 = (rem / (Fq / 32)) * 32;
        const int tx = tid & 31, ty = tid >> 5;
        for (int r = ty; r < 32; r += 8)
            tile[r][tx] = h[((size_t)o * Lq + t0 + r) * Fq + f0 + tx];
        __syncthreads();
        for (int r = ty; r < 32; r += 8)
            g_ht[((size_t)(o * Fq + f0 + r)) * Lq + t0 + tx] = tile[tx][r];
    }
}

// ---------------- register FFT machinery ------------------------------------
__device__ __constant__ float W32C[16] = {
    1.0f, 0.9807852804032304f, 0.9238795325112867f, 0.8314696123025452f,
    0.7071067811865476f, 0.5555702330196022f, 0.3826834323650898f, 0.19509032201612825f,
    0.0f, -0.19509032201612825f, -0.3826834323650898f, -0.5555702330196022f,
    -0.7071067811865476f, -0.8314696123025452f, -0.9238795325112867f, -0.9807852804032304f };
__device__ __constant__ float W32S[16] = {
    0.0f, -0.19509032201612825f, -0.3826834323650898f, -0.5555702330196022f,
    -0.7071067811865476f, -0.8314696123025452f, -0.9238795325112867f, -0.9807852804032304f,
    -1.0f, -0.9807852804032304f, -0.9238795325112867f, -0.8314696123025452f,
    -0.7071067811865476f, -0.5555702330196022f, -0.3826834323650898f, -0.19509032201612825f };

#define SWAPC(a, b) { float t_ = xr[a]; xr[a] = xr[b]; xr[b] = t_; \
                      t_ = xi[a]; xi[a] = xi[b]; xi[b] = t_; }

template<int DIR>
__device__ __forceinline__ void fft32r(float* xr, float* xi) {
    SWAPC(1,16)  SWAPC(2,8)   SWAPC(3,24)  SWAPC(5,20)
    SWAPC(6,12)  SWAPC(7,28)  SWAPC(9,18)  SWAPC(11,26)
    SWAPC(13,22) SWAPC(15,30) SWAPC(19,25) SWAPC(23,29)
    #pragma unroll
    for (int s = 1; s <= 5; s++) {
        const int half = 1 << (s - 1);
        #pragma unroll
        for (int k = 0; k < 16; k++) {
            int j  = k & (half - 1);
            int i1 = ((k >> (s - 1)) << s) + j;
            int i2 = i1 + half;
            int w  = j * (32 >> s);
            float cs = W32C[w];
            float sn = (DIR < 0) ? W32S[w] : -W32S[w];
            float tr = xr[i2] * cs - xi[i2] * sn;
            float ti = xr[i2] * sn + xi[i2] * cs;
            xr[i2] = xr[i1] - tr; xi[i2] = xi[i1] - ti;
            xr[i1] += tr;         xi[i1] += ti;
        }
    }
}
template<int DIR>
__device__ __forceinline__ void fft16r(float* xr, float* xi) {
    SWAPC(1,8) SWAPC(2,4) SWAPC(3,12) SWAPC(5,10) SWAPC(7,14) SWAPC(11,13)
    #pragma unroll
    for (int s = 1; s <= 4; s++) {
        const int half = 1 << (s - 1);
        #pragma unroll
        for (int k = 0; k < 8; k++) {
            int j  = k & (half - 1);
            int i1 = ((k >> (s - 1)) << s) + j;
            int i2 = i1 + half;
            int w  = j * (32 >> s);
            float cs = W32C[w];
            float sn = (DIR < 0) ? W32S[w] : -W32S[w];
            float tr = xr[i2] * cs - xi[i2] * sn;
            float ti = xr[i2] * sn + xi[i2] * cs;
            xr[i2] = xr[i1] - tr; xi[i2] = xi[i1] - ti;
            xr[i1] += tr;         xi[i1] += ti;
        }
    }
}
#undef SWAPC

// ---- 8192-pt FFT (256 threads, 32 regs): passes 32 x 16 x 16 ---------------
// If WB: natural-order in RE/IM (+final sync). If !WB: pass-3 results in regs;
// map: xr[j2] <-> n = (tid&31) + 32*(tid>>5) + 512*j2, xr[16+j2] <-> n + 256.
template<int DIR, bool WB>
__device__ __forceinline__ void fft8k(float* RE, float* IM, float* xr, float* xi, int tid) {
    const float TW = (DIR < 0) ? -6.2831853071795864769f : 6.2831853071795864769f;
    fft32r<DIR>(xr, xi);
    {
        const float ang1 = TW * (float)tid * (1.0f / 8192.0f);
        RE[tid] = xr[0]; IM[tid] = xi[0];
        #pragma unroll
        for (int k1 = 1; k1 < 32; k1++) {
            float sn, cs;
            __sincosf(ang1 * (float)k1, &sn, &cs);
            RE[k1 * 272 + tid] = xr[k1] * cs - xi[k1] * sn;
            IM[k1 * 272 + tid] = xr[k1] * sn + xi[k1] * cs;
        }
    }
    __syncthreads();
    {
        int k1a = tid >> 4, m2 = tid & 15;
        int k1b = k1a + 16;
        #pragma unroll
        for (int m1 = 0; m1 < 16; m1++) {
            xr[m1]      = RE[k1a * 272 + m1 * 16 + m2];
            xi[m1]      = IM[k1a * 272 + m1 * 16 + m2];
            xr[16 + m1] = RE[k1b * 272 + m1 * 16 + m2];
            xi[16 + m1] = IM[k1b * 272 + m1 * 16 + m2];
        }
        __syncthreads();
        fft16r<DIR>(xr, xi);
        fft16r<DIR>(xr + 16, xi + 16);
        const float ang2 = TW * (float)m2 * (1.0f / 256.0f);
        int wba = k1a * 17 + m2, wbb = k1b * 17 + m2;
        RE[wba] = xr[0];  IM[wba] = xi[0];
        RE[wbb] = xr[16]; IM[wbb] = xi[16];
        #pragma unroll
        for (int j1 = 1; j1 < 16; j1++) {
            float sn, cs;
            __sincosf(ang2 * (float)j1, &sn, &cs);
            RE[j1 * 544 + wba] = xr[j1] * cs - xi[j1] * sn;
            IM[j1 * 544 + wba] = xr[j1] * sn + xi[j1] * cs;
            RE[j1 * 544 + wbb] = xr[16 + j1] * cs - xi[16 + j1] * sn;
            IM[j1 * 544 + wbb] = xr[16 + j1] * sn + xi[16 + j1] * cs;
        }
    }
    __syncthreads();
    {
        int k1 = tid & 31, j1a = tid >> 5, j1b = j1a + 8;
        #pragma unroll
        for (int m2 = 0; m2 < 16; m2++) {
            xr[m2]      = RE[j1a * 544 + k1 * 17 + m2];
            xi[m2]      = IM[j1a * 544 + k1 * 17 + m2];
            xr[16 + m2] = RE[j1b * 544 + k1 * 17 + m2];
            xi[16 + m2] = IM[j1b * 544 + k1 * 17 + m2];
        }
        if (WB) __syncthreads();
        fft16r<DIR>(xr, xi);
        fft16r<DIR>(xr + 16, xi + 16);
        if (WB) {
            #pragma unroll
            for (int j2 = 0; j2 < 16; j2++) {
                RE[k1 + 32 * j1a + 512 * j2] = xr[j2];
                IM[k1 + 32 * j1a + 512 * j2] = xi[j2];
                RE[k1 + 32 * j1b + 512 * j2] = xr[16 + j2];
                IM[k1 + 32 * j1b + 512 * j2] = xi[16 + j2];
            }
            __syncthreads();
        }
    }
}
#define CH_SMEM_FLOATS 8704

// ---------------- GEMM chunk-order helpers (shared-tile reuse) --------------
// Chunk order per kc: (sg1: A1*B0), (sg0: A0*B0), (sg2: A0*B1)
// j = c%3:  j=0: A=Aj0 (new), B=B01 (new)
//           j=1: A=A12 (new), B=B01 (reuse)
//           j=2: A=A12 (reuse), B=B2 (new)
// A-slot = (2*kc + (j>=1)) % 3;  B-slot = (2*kc + (j==2)) % 3.

// ---------------- K1: up = u @ w_in + b_in (256 thr, 128x128, 3-ring) ------
#define UPA_STG 9216
#define UPB_STG 8704
#define UP_SMEM ((3 * UPA_STG + 3 * UPB_STG) * 2)   // 107520 B

__device__ __forceinline__ void up_loadA(__nv_bfloat16* dst, const __nv_bfloat16* Ap,
                                         int m0, int k0, int tid) {
    #pragma unroll
    for (int it = 0; it < 4; it++) {
        int id = tid + it * 256, r = id >> 3, cu = id & 7;
        cp16(cvta_s(dst + r * 72 + cu * 8), Ap + (size_t)(m0 + r) * Fq + k0 + cu * 8);
    }
}
__device__ __forceinline__ void up_loadB(__nv_bfloat16* dst, const __nv_bfloat16* Bp,
                                         int n0, int k0, int tid) {
    #pragma unroll
    for (int it = 0; it < 4; it++) {
        int id = tid + it * 256, r = id >> 4, cu = id & 15;
        cp16(cvta_s(dst + r * 136 + cu * 8), Bp + (size_t)(k0 + r) * IWq + n0 + cu * 8);
    }
}

__global__ void __launch_bounds__(256) gemm_up_tc(const float* __restrict__ bias) {
    extern __shared__ __align__(16) __nv_bfloat16 smp[];
    __nv_bfloat16* As = smp;
    __nv_bfloat16* Bs = smp + 3 * UPA_STG;
    const int m0 = blockIdx.y * 128, n0 = blockIdx.x * 128;
    const int tid = threadIdx.x, lane = tid & 31, wid = tid >> 5;
    const int wm = wid >> 2, wn = wid & 3;
    float acc[4][4][4] = {};

    // prologue: chunk 0 (A=ul slot0, B=wih slot0), chunk 1 (A=uh slot1)
    up_loadA(As, g_ul, m0, 0, tid);
    up_loadB(Bs, g_wih, n0, 0, tid);
    cp_commit();
    up_loadA(As + UPA_STG, g_uh, m0, 0, tid);
    cp_commit();

    for (int c = 0; c < 36; c++) {
        if (c < 35) cp_wait1(); else cp_wait0();
        __syncthreads();
        int pf = c + 2;
        if (pf < 36) {
            int kcp = pf / 3, jp = pf % 3;
            if (jp <= 1)
                up_loadA(As + ((2 * kcp + (jp >= 1)) % 3) * UPA_STG,
                         (jp == 0) ? g_ul : g_uh, m0, kcp * 64, tid);
            if (jp != 1)
                up_loadB(Bs + ((2 * kcp + (jp == 2)) % 3) * UPB_STG,
                         (jp == 2) ? g_wil : g_wih, n0, kcp * 64, tid);
            cp_commit();
        }
        int kc = c / 3, j = c % 3;
        const __nv_bfloat16* Ab = As + ((2 * kc + (j >= 1)) % 3) * UPA_STG;
        const __nv_bfloat16* Bb = Bs + ((2 * kc + (j == 2)) % 3) * UPB_STG;
        #pragma unroll
        for (int ks = 0; ks < 4; ks++) {
            uint32_t a[4][4], bf[4][2];
            #pragma unroll
            for (int mi = 0; mi < 4; mi++) {
                const __nv_bfloat16* p = Ab + (wm * 64 + mi * 16 + (lane & 15)) * 72
                                            + ks * 16 + (lane >> 4) * 8;
                ldsm_x4(a[mi][0], a[mi][1], a[mi][2], a[mi][3], cvta_s(p));
            }
            #pragma unroll
            for (int pr = 0; pr < 2; pr++) {
                const __nv_bfloat16* p = Bb + (ks * 16 + (lane & 15)) * 136
                                            + wn * 32 + pr * 16 + (lane >> 4) * 8;
                ldsm_x4_t(bf[2*pr][0], bf[2*pr][1], bf[2*pr+1][0], bf[2*pr+1][1], cvta_s(p));
            }
            #pragma unroll
            for (int mi = 0; mi < 4; mi++)
                #pragma unroll
                for (int ni = 0; ni < 4; ni++)
                    mma_bf16(acc[mi][ni], a[mi], bf[ni]);
        }
    }
    #pragma unroll
    for (int mi = 0; mi < 4; mi++)
        #pragma unroll
        for (int ni = 0; ni < 4; ni++) {
            int row = m0 + wm * 64 + mi * 16 + (lane >> 2);
            int col = n0 + wn * 32 + ni * 8 + (lane & 3) * 2;
            float b0 = bias[col], b1 = bias[col + 1];
            *(float2*)&g_up[(size_t)row * IWq + col] =
                make_float2(acc[mi][ni][0] + b0, acc[mi][ni][1] + b1);
            *(float2*)&g_up[(size_t)(row + 8) * IWq + col] =
                make_float2(acc[mi][ni][2] + b0, acc[mi][ni][3] + b1);
        }
}

// ---------------- K2: depthwise conv + split + gate (float4 loads) ---------
__global__ void __launch_bounds__(256) conv_gate(const float* __restrict__ convk,
                                                 const float* __restrict__ convb) {
    __shared__ float s_in[34 * 4 * 32];
    __shared__ float s_out[3][32][33];
    const int f0 = blockIdx.x * 32, t0 = blockIdx.y * 32, b = blockIdx.z;
    const int tid = threadIdx.x, tx = tid & 31, ty = tid >> 5;

    for (int q = tid; q < 136 * 8; q += 256) {
        int row = q >> 3, w = q & 7;
        int tt = row >> 2, c4 = row & 3;
        int t = t0 - 2 + tt;
        float4 v = make_float4(0.f, 0.f, 0.f, 0.f);
        if (t >= 0)
            v = *(const float4*)&g_up[(size_t)(b * Lq + t) * IWq + c4 * Fq + f0 + w * 4];
        *(float4*)&s_in[row * 32 + w * 4] = v;
    }
    float kk[4][3], cb[4];
    #pragma unroll
    for (int c4 = 0; c4 < 4; c4++) {
        int c = c4 * Fq + f0 + tx;
        kk[c4][0] = convk[c]; kk[c4][1] = convk[IWq + c]; kk[c4][2] = convk[2 * IWq + c];
        cb[c4] = convb[c];
    }
    __syncthreads();
    #pragma unroll
    for (int q = 0; q < 4; q++) {
        int ts = ty + 8 * q;
        float o[4];
        #pragma unroll
        for (int c4 = 0; c4 < 4; c4++)
            o[c4] = cb[c4]
                  + kk[c4][2] * s_in[((ts + 2) * 4 + c4) * 32 + tx]
                  + kk[c4][1] * s_in[((ts + 1) * 4 + c4) * 32 + tx]
                  + kk[c4][0] * s_in[((ts    ) * 4 + c4) * 32 + tx];
        s_out[0][tx][ts] = o[3] * o[0];
        s_out[1][tx][ts] = o[1];
        s_out[2][tx][ts] = o[2];
    }
    __syncthreads();
    float* dst[3] = { g_v, g_x1, g_x2 };
    #pragma unroll
    for (int jn = 0; jn < 3; jn++)
        #pragma unroll
        for (int qq = 0; qq < 4; qq++) {
            int fr = ty + 8 * qq;
            dst[jn][(size_t)(b * Fq + f0 + fr) * Lq + t0 + tx] = s_out[jn][fr][tx];
        }
}

// ---------------- K3: per-(o,f) 8192-pt real-packed FFT of h ---------------
__global__ void __launch_bounds__(256) hfft_kernel() {
    extern __shared__ float sm[];
    float* RE = sm;
    float* IM = sm + CH_SMEM_FLOATS;
    const int idx = blockIdx.x;           // o * Fq + f
    const int tid = threadIdx.x;
    const float* hsrc = g_ht + (size_t)idx * Lq;
    float xr[32], xi[32];
    #pragma unroll
    for (int n1 = 0; n1 < 32; n1++) {
        if (n1 < 16) {
            float2 hh = *(const float2*)&hsrc[2 * (n1 * 256 + tid)];
            xr[n1] = hh.x; xi[n1] = hh.y;
        } else { xr[n1] = 0.0f; xi[n1] = 0.0f; }
    }
    fft8k<-1, true>(RE, IM, xr, xi, tid);     // Z natural-order in RE/IM
    float2* H = g_H + (size_t)idx * HSTR;
    #pragma unroll
    for (int n1 = 0; n1 < 32; n1++) {
        int k   = n1 * 256 + tid;
        int kks = (8192 - k) & 8191;
        float zr = RE[k],   zi = IM[k];
        float wr = RE[kks], wi = IM[kks];
        float zer = 0.5f * (zr + wr), zei = 0.5f * (zi - wi);
        float zor = 0.5f * (zi + wi), zoi = 0.5f * (wr - zr);
        float sn, cs;
        __sincosf(-6.2831853071795864769f * (float)k * (1.0f / 16384.0f), &sn, &cs);
        H[k] = make_float2(zer + cs * zor - sn * zoi,
                           zei + cs * zoi + sn * zor);
    }
    if (tid == 0)
        H[8192] = make_float2(RE[0] - IM[0], 0.0f);   // V[8192] = ReZ0 - ImZ0
}

// ---------------- K4: per-(b, f) chain via 8192-pt real-packed FFT ---------
__global__ void __launch_bounds__(256) chain_kernel(const float* __restrict__ bias) {
    extern __shared__ float sm[];
    float* RE = sm;
    float* IM = sm + CH_SMEM_FLOATS;
    const int idx = blockIdx.x;           // b * Fq + f
    const int b = idx / Fq, f = idx % Fq;
    const int tid = threadIdx.x;
    const size_t base = ((size_t)b * Fq + f) * Lq;
    const float inv = 1.0f / 8192.0f;
    float xr[32], xi[32];

    #pragma unroll 1
    for (int o = 0; o < 2; o++) {
        #pragma unroll
        for (int n1 = 0; n1 < 32; n1++) {
            if (n1 < 16) {
                float2 vv = *(const float2*)&g_v[base + 2 * (n1 * 256 + tid)];
                xr[n1] = vv.x; xi[n1] = vv.y;
            } else { xr[n1] = 0.0f; xi[n1] = 0.0f; }
        }
        __syncthreads();
        fft8k<-1, true>(RE, IM, xr, xi, tid);

        const float2* Hf = g_H + ((size_t)o * Fq + f) * HSTR;
        #pragma unroll
        for (int n1 = 0; n1 < 32; n1++) {
            int k   = n1 * 256 + tid;
            int kks = (8192 - k) & 8191;
            int kp  = 8192 - k;
            float zr = RE[k],   zi = IM[k];
            float wr = RE[kks], wi = IM[kks];
            float zer = 0.5f * (zr + wr), zei = 0.5f * (zi - wi);
            float zor = 0.5f * (zi + wi), zoi = 0.5f * (wr - zr);
            float sn, cs;
            __sincosf(-6.2831853071795864769f * (float)k * (1.0f / 16384.0f), &sn, &cs);
            float vkr = zer + cs * zor - sn * zoi;
            float vki = zei + cs * zoi + sn * zor;
            float vpr = zer - cs * zor + sn * zoi;
            float vpi = -zei + cs * zoi + sn * zor;
            float2 hk = Hf[k], hp = Hf[kp];
            float ykr = vkr * hk.x - vki * hk.y, yki = vkr * hk.y + vki * hk.x;
            float ypr = vpr * hp.x - vpi * hp.y, ypi = vpr * hp.y + vpi * hp.x;
            float er  = 0.5f * (ykr + ypr), ei  = 0.5f * (yki - ypi);
            float ocr = 0.5f * (ykr - ypr), oci = 0.5f * (yki + ypi);
            float orr = cs * ocr + sn * oci;
            float ori = cs * oci - sn * ocr;
            xr[n1] = er - ori;
            xi[n1] = ei + orr;
        }
        __syncthreads();
        fft8k<1, false>(RE, IM, xr, xi, tid);

        const float bo = bias[o * Fq + f];
        const float* X = (o == 0 ? g_x1 : g_x2) + base;
        const int k1 = tid & 31, j1a = tid >> 5;
        if (o == 0) {
            #pragma unroll
            for (int j2 = 0; j2 < 8; j2++) {
                int n  = k1 + 32 * j1a + 512 * j2;
                int n2 = n + 256;
                float2 vo = *(const float2*)&g_v[base + 2 * n];
                float2 xg = *(const float2*)&X[2 * n];
                float2 w;
                w.x = (xr[j2] * inv + vo.x * bo) * xg.x;
                w.y = (xi[j2] * inv + vo.y * bo) * xg.y;
                *(float2*)&g_v[base + 2 * n] = w;
                float2 vo2 = *(const float2*)&g_v[base + 2 * n2];
                float2 xg2 = *(const float2*)&X[2 * n2];
                float2 w2;
                w2.x = (xr[16 + j2] * inv + vo2.x * bo) * xg2.x;
                w2.y = (xi[16 + j2] * inv + vo2.y * bo) * xg2.y;
                *(float2*)&g_v[base + 2 * n2] = w2;
            }
        } else {
            #pragma unroll
            for (int j2 = 0; j2 < 8; j2++) {
                int n  = k1 + 32 * j1a + 512 * j2;
                int n2 = n + 256;
                float2 vo = *(const float2*)&g_v[base + 2 * n];
                float2 xg = *(const float2*)&X[2 * n];
                float y0 = (xr[j2] * inv + vo.x * bo) * xg.x;
                float y1 = (xi[j2] * inv + vo.y * bo) * xg.y;
                __nv_bfloat16 h0 = __float2bfloat16(y0);
                __nv_bfloat16 h1 = __float2bfloat16(y1);
                g_vh[base + 2 * n]     = h0;
                g_vh[base + 2 * n + 1] = h1;
                g_vl[base + 2 * n]     = __float2bfloat16(y0 - __bfloat162float(h0));
                g_vl[base + 2 * n + 1] = __float2bfloat16(y1 - __bfloat162float(h1));
                float2 vo2 = *(const float2*)&g_v[base + 2 * n2];
                float2 xg2 = *(const float2*)&X[2 * n2];
                float y2 = (xr[16 + j2] * inv + vo2.x * bo) * xg2.x;
                float y3 = (xi[16 + j2] * inv + vo2.y * bo) * xg2.y;
                __nv_bfloat16 h2 = __float2bfloat16(y2);
                __nv_bfloat16 h3 = __float2bfloat16(y3);
                g_vh[base + 2 * n2]     = h2;
                g_vh[base + 2 * n2 + 1] = h3;
                g_vl[base + 2 * n2]     = __float2bfloat16(y2 - __bfloat162float(h2));
                g_vl[base + 2 * n2 + 1] = __float2bfloat16(y3 - __bfloat162float(h3));
            }
        }
        __syncthreads();
    }
}

// ---------------- K5: out = v2 @ w_out + b_out (256 thr, 128x128, 3-ring) --
#define OTA_STG 8704
#define OTB_STG 8704
#define OT_SMEM ((3 * OTA_STG + 3 * OTB_STG) * 2)   // 104448 B

__device__ __forceinline__ void out_loadA(__nv_bfloat16* dst, const __nv_bfloat16* Ap,
                                          int t0, int k0, int tid) {
    #pragma unroll
    for (int it = 0; it < 4; it++) {
        int id = tid + it * 256, r = id >> 4, cu = id & 15;
        cp16(cvta_s(dst + r * 136 + cu * 8), Ap + (size_t)(k0 + r) * Lq + t0 + cu * 8);
    }
}
__device__ __forceinline__ void out_loadB(__nv_bfloat16* dst, const __nv_bfloat16* Bp,
                                          int n0, int k0, int tid) {
    #pragma unroll
    for (int it = 0; it < 4; it++) {
        int id = tid + it * 256, r = id >> 4, cu = id & 15;
        cp16(cvta_s(dst + r * 136 + cu * 8), Bp + (size_t)(k0 + r) * Fq + n0 + cu * 8);
    }
}

__global__ void __launch_bounds__(256) gemm_out_tc(const float* __restrict__ bias,
                                                   float* __restrict__ out) {
    extern __shared__ __align__(16) __nv_bfloat16 smp[];
    __nv_bfloat16* As = smp;
    __nv_bfloat16* Bs = smp + 3 * OTA_STG;
    const int m0 = blockIdx.y * 128, n0 = blockIdx.x * 128;
    const int b = m0 / Lq, t0 = m0 % Lq;
    const int tid = threadIdx.x, lane = tid & 31, wid = tid >> 5;
    const int wm = wid >> 2, wn = wid & 3;
    float acc[4][4][4] = {};

    const size_t abase = (size_t)b * Fq * Lq;
    const __nv_bfloat16* Avh = g_vh + abase;
    const __nv_bfloat16* Avl = g_vl + abase;

    // prologue: chunk 0 (A=vl slot0, B=woh slot0), chunk 1 (A=vh slot1)
    out_loadA(As, Avl, t0, 0, tid);
    out_loadB(Bs, g_woh, n0, 0, tid);
    cp_commit();
    out_loadA(As + OTA_STG, Avh, t0, 0, tid);
    cp_commit();

    for (int c = 0; c < 36; c++) {
        if (c < 35) cp_wait1(); else cp_wait0();
        __syncthreads();
        int pf = c + 2;
        if (pf < 36) {
            int kcp = pf / 3, jp = pf % 3;
            if (jp <= 1)
                out_loadA(As + ((2 * kcp + (jp >= 1)) % 3) * OTA_STG,
                          (jp == 0) ? Avl : Avh, t0, kcp * 64, tid);
            if (jp != 1)
                out_loadB(Bs + ((2 * kcp + (jp == 2)) % 3) * OTB_STG,
                          (jp == 2) ? g_wol : g_woh, n0, kcp * 64, tid);
            cp_commit();
        }
        int kc = c / 3, j = c % 3;
        const __nv_bfloat16* Ab = As + ((2 * kc + (j >= 1)) % 3) * OTA_STG;
        const __nv_bfloat16* Bb = Bs + ((2 * kc + (j == 2)) % 3) * OTB_STG;
        #pragma unroll
        for (int ks = 0; ks < 4; ks++) {
            uint32_t a[4][4], bf[4][2];
            #pragma unroll
            for (int mi = 0; mi < 4; mi++) {
                int krow = ks * 16 + ((lane >> 4) ? 8 : 0) + (lane & 7);
                int mcol = wm * 64 + mi * 16 + ((lane >> 3) & 1) * 8;
                const __nv_bfloat16* p = Ab + krow * 136 + mcol;
                ldsm_x4_t(a[mi][0], a[mi][1], a[mi][2], a[mi][3], cvta_s(p));
            }
            #pragma unroll
            for (int pr = 0; pr < 2; pr++) {
                const __nv_bfloat16* p = Bb + (ks * 16 + (lane & 15)) * 136
                                            + wn * 32 + pr * 16 + (lane >> 4) * 8;
                ldsm_x4_t(bf[2*pr][0], bf[2*pr][1], bf[2*pr+1][0], bf[2*pr+1][1], cvta_s(p));
            }
            #pragma unroll
            for (int mi = 0; mi < 4; mi++)
                #pragma unroll
                for (int ni = 0; ni < 4; ni++)
                    mma_bf16(acc[mi][ni], a[mi], bf[ni]);
        }
    }
    #pragma unroll
    for (int mi = 0; mi < 4; mi++)
        #pragma unroll
        for (int ni = 0; ni < 4; ni++) {
            int row = m0 + wm * 64 + mi * 16 + (lane >> 2);
            int col = n0 + wn * 32 + ni * 8 + (lane & 3) * 2;
            float b0 = bias[col], b1 = bias[col + 1];
            *(float2*)&out[(size_t)row * Fq + col] =
                make_float2(acc[mi][ni][0] + b0, acc[mi][ni][1] + b1);
            *(float2*)&out[(size_t)(row + 8) * Fq + col] =
                make_float2(acc[mi][ni][2] + b0, acc[mi][ni][3] + b1);
        }
}

// ---------------- launch -----------------------------------------------------
extern "C" void kernel_launch(void* const* d_in, const int* in_sizes, int n_in,
                              void* d_out, int out_size) {
    const float* u      = (const float*)d_in[0];
    const float* h      = (const float*)d_in[1];
    const float* bias   = (const float*)d_in[2];
    const float* w_in   = (const float*)d_in[3];
    const float* b_in   = (const float*)d_in[4];
    const float* conv_k = (const float*)d_in[5];
    const float* conv_b = (const float*)d_in[6];
    const float* w_out  = (const float*)d_in[7];
    const float* b_out  = (const float*)d_in[8];
    float* out = (float*)d_out;

    const int ch_smem = CH_SMEM_FLOATS * 2 * sizeof(float);    // 69632
    cudaFuncSetAttribute(hfft_kernel,  cudaFuncAttributeMaxDynamicSharedMemorySize, ch_smem);
    cudaFuncSetAttribute(chain_kernel, cudaFuncAttributeMaxDynamicSharedMemorySize, ch_smem);
    cudaFuncSetAttribute(gemm_up_tc,   cudaFuncAttributeMaxDynamicSharedMemorySize, UP_SMEM);
    cudaFuncSetAttribute(gemm_out_tc,  cudaFuncAttributeMaxDynamicSharedMemorySize, OT_SMEM);

    prep_kernel<<<NB_U + NB_WI + NB_WO + NB_T, 256>>>(u, w_in, w_out, h);
    hfft_kernel<<<2 * Fq, 256, ch_smem>>>();
    gemm_up_tc<<<dim3(IWq / 128, Mq / 128), 256, UP_SMEM>>>(b_in);
    conv_gate<<<dim3(Fq / 32, Lq / 32, Bq), 256>>>(conv_k, conv_b);
    chain_kernel<<<Bq * Fq, 256, ch_smem>>>(bias);
    gemm_out_tc<<<dim3(Fq / 128, Mq / 128), 256, OT_SMEM>>>(b_out, out);
}

// round 17
// speedup vs baseline: 1.2120x; 1.0638x over previous
#include <cuda_runtime.h>
#include <cuda_bf16.h>
#include <cstdint>

#define Bq   2
#define Fq   768
#define Lq   8192
#define IWq  3072
#define NFFT 16384
#define Mq   (Bq * Lq)          // 16384
#define HSTR 8256               // padded half-spectrum stride (>= 8193)

// ---------------- scratch (device globals; no allocations) ----------------
__device__ __align__(16) float  g_up[(size_t)Mq * IWq];
__device__ __align__(16) float  g_v [(size_t)Bq * Fq * Lq];   // [b][f][t]
__device__ __align__(16) float  g_x1[(size_t)Bq * Fq * Lq];
__device__ __align__(16) float  g_x2[(size_t)Bq * Fq * Lq];
__device__ __align__(16) float  g_ht[(size_t)2 * Fq * Lq];    // h transposed [o][f][t]
__device__ __align__(16) float2 g_H [(size_t)2 * Fq * HSTR];  // half spectra of h
__device__ __align__(16) __nv_bfloat16 g_uh [(size_t)Mq * Fq];
__device__ __align__(16) __nv_bfloat16 g_ul [(size_t)Mq * Fq];
__device__ __align__(16) __nv_bfloat16 g_wih[(size_t)Fq * IWq];   // w_in [k][n]
__device__ __align__(16) __nv_bfloat16 g_wil[(size_t)Fq * IWq];
__device__ __align__(16) __nv_bfloat16 g_woh[(size_t)Fq * Fq];    // w_out [k][n]
__device__ __align__(16) __nv_bfloat16 g_wol[(size_t)Fq * Fq];
__device__ __align__(16) __nv_bfloat16 g_vh [(size_t)Bq * Fq * Lq];
__device__ __align__(16) __nv_bfloat16 g_vl [(size_t)Bq * Fq * Lq];

// ---------------- helpers ---------------------------------------------------
__device__ __forceinline__ uint32_t cvta_s(const void* p) {
    return (uint32_t)__cvta_generic_to_shared(p);
}
__device__ __forceinline__ void cp16(uint32_t dst, const void* src) {
    asm volatile("cp.async.cg.shared.global [%0], [%1], 16;\n" :: "r"(dst), "l"(src));
}
__device__ __forceinline__ void cp_commit() { asm volatile("cp.async.commit_group;\n"); }
__device__ __forceinline__ void cp_wait1()  { asm volatile("cp.async.wait_group 1;\n"); }
__device__ __forceinline__ void cp_wait0()  { asm volatile("cp.async.wait_group 0;\n"); }

__device__ __forceinline__ void ldsm_x4(uint32_t& r0, uint32_t& r1, uint32_t& r2, uint32_t& r3, uint32_t a) {
    asm volatile("ldmatrix.sync.aligned.m8n8.x4.shared.b16 {%0,%1,%2,%3}, [%4];\n"
                 : "=r"(r0), "=r"(r1), "=r"(r2), "=r"(r3) : "r"(a));
}
__device__ __forceinline__ void ldsm_x4_t(uint32_t& r0, uint32_t& r1, uint32_t& r2, uint32_t& r3, uint32_t a) {
    asm volatile("ldmatrix.sync.aligned.m8n8.x4.trans.shared.b16 {%0,%1,%2,%3}, [%4];\n"
                 : "=r"(r0), "=r"(r1), "=r"(r2), "=r"(r3) : "r"(a));
}
__device__ __forceinline__ void mma_bf16(float* d, const uint32_t* a, const uint32_t* b) {
    asm volatile("mma.sync.aligned.m16n8k16.row.col.f32.bf16.bf16.f32 "
                 "{%0,%1,%2,%3},{%4,%5,%6,%7},{%8,%9},{%0,%1,%2,%3};\n"
                 : "+f"(d[0]), "+f"(d[1]), "+f"(d[2]), "+f"(d[3])
                 : "r"(a[0]), "r"(a[1]), "r"(a[2]), "r"(a[3]), "r"(b[0]), "r"(b[1]));
}

// ---------------- prep: fused vectorized cvt_splits + transpose_h ----------
#define NB_U  ((Mq * Fq) / 1024)       // 12288
#define NB_WI ((Fq * IWq) / 1024)      // 2304
#define NB_WO ((Fq * Fq) / 1024)       // 576
#define NB_T  (2 * (Fq / 32) * (Lq / 32))  // 12288

__global__ void __launch_bounds__(256) prep_kernel(const float* __restrict__ u,
                                                   const float* __restrict__ w_in,
                                                   const float* __restrict__ w_out,
                                                   const float* __restrict__ h) {
    __shared__ float tile[32][33];
    const int bid = blockIdx.x, tid = threadIdx.x;
    if (bid < NB_U + NB_WI + NB_WO) {
        const float* s;
        __nv_bfloat16 *hi, *lo;
        int i;
        if (bid < NB_U) {
            s = u; hi = g_uh; lo = g_ul; i = (bid * 256 + tid) * 4;
        } else if (bid < NB_U + NB_WI) {
            s = w_in; hi = g_wih; lo = g_wil; i = ((bid - NB_U) * 256 + tid) * 4;
        } else {
            s = w_out; hi = g_woh; lo = g_wol; i = ((bid - NB_U - NB_WI) * 256 + tid) * 4;
        }
        float4 x = *(const float4*)(s + i);
        __nv_bfloat16 h0 = __float2bfloat16(x.x);
        __nv_bfloat16 h1 = __float2bfloat16(x.y);
        __nv_bfloat16 h2 = __float2bfloat16(x.z);
        __nv_bfloat16 h3 = __float2bfloat16(x.w);
        __nv_bfloat16 l0 = __float2bfloat16(x.x - __bfloat162float(h0));
        __nv_bfloat16 l1 = __float2bfloat16(x.y - __bfloat162float(h1));
        __nv_bfloat16 l2 = __float2bfloat16(x.z - __bfloat162float(h2));
        __nv_bfloat16 l3 = __float2bfloat16(x.w - __bfloat162float(h3));
        __nv_bfloat162 ph0 = __nv_bfloat162(h0, h1), ph1 = __nv_bfloat162(h2, h3);
        __nv_bfloat162 pl0 = __nv_bfloat162(l0, l1), pl1 = __nv_bfloat162(l2, l3);
        uint2 wh, wl;
        wh.x = *(uint32_t*)&ph0; wh.y = *(uint32_t*)&ph1;
        wl.x = *(uint32_t*)&pl0; wl.y = *(uint32_t*)&pl1;
        *(uint2*)(hi + i) = wh;
        *(uint2*)(lo + i) = wl;
    } else {
        int fb = bid - (NB_U + NB_WI + NB_WO);
        int o = fb / ((Fq / 32) * (Lq / 32));
        int rem = fb % ((Fq / 32) * (Lq / 32));
        int f0 = (rem % (Fq / 32)) * 32;
        int t0 = (rem / (Fq / 32)) * 32;
        const int tx = tid & 31, ty = tid >> 5;
        for (int r = ty; r < 32; r += 8)
            tile[r][tx] = h[((size_t)o * Lq + t0 + r) * Fq + f0 + tx];
        __syncthreads();
        for (int r = ty; r < 32; r += 8)
            g_ht[((size_t)(o * Fq + f0 + r)) * Lq + t0 + tx] = tile[tx][r];
    }
}

// ---------------- register FFT machinery ------------------------------------
// Twiddles as function-local literal arrays: indices are compile-time after
// unroll, so nvcc constant-folds every butterfly (trivial ones collapse).
#define SWAPC(a, b) { float t_ = xr[a]; xr[a] = xr[b]; xr[b] = t_; \
                      t_ = xi[a]; xi[a] = xi[b]; xi[b] = t_; }

template<int DIR>
__device__ __forceinline__ void fft32r(float* xr, float* xi) {
    const float LC[16] = {
        1.0f, 0.9807852804032304f, 0.9238795325112867f, 0.8314696123025452f,
        0.7071067811865476f, 0.5555702330196022f, 0.3826834323650898f, 0.19509032201612825f,
        0.0f, -0.19509032201612825f, -0.3826834323650898f, -0.5555702330196022f,
        -0.7071067811865476f, -0.8314696123025452f, -0.9238795325112867f, -0.9807852804032304f };
    const float LS[16] = {
        0.0f, -0.19509032201612825f, -0.3826834323650898f, -0.5555702330196022f,
        -0.7071067811865476f, -0.8314696123025452f, -0.9238795325112867f, -0.9807852804032304f,
        -1.0f, -0.9807852804032304f, -0.9238795325112867f, -0.8314696123025452f,
        -0.7071067811865476f, -0.5555702330196022f, -0.3826834323650898f, -0.19509032201612825f };
    SWAPC(1,16)  SWAPC(2,8)   SWAPC(3,24)  SWAPC(5,20)
    SWAPC(6,12)  SWAPC(7,28)  SWAPC(9,18)  SWAPC(11,26)
    SWAPC(13,22) SWAPC(15,30) SWAPC(19,25) SWAPC(23,29)
    #pragma unroll
    for (int s = 1; s <= 5; s++) {
        const int half = 1 << (s - 1);
        #pragma unroll
        for (int k = 0; k < 16; k++) {
            int j  = k & (half - 1);
            int i1 = ((k >> (s - 1)) << s) + j;
            int i2 = i1 + half;
            int w  = j * (32 >> s);
            float cs = LC[w];
            float sn = (DIR < 0) ? LS[w] : -LS[w];
            float tr = xr[i2] * cs - xi[i2] * sn;
            float ti = xr[i2] * sn + xi[i2] * cs;
            xr[i2] = xr[i1] - tr; xi[i2] = xi[i1] - ti;
            xr[i1] += tr;         xi[i1] += ti;
        }
    }
}
template<int DIR>
__device__ __forceinline__ void fft16r(float* xr, float* xi) {
    const float LC[16] = {
        1.0f, 0.9807852804032304f, 0.9238795325112867f, 0.8314696123025452f,
        0.7071067811865476f, 0.5555702330196022f, 0.3826834323650898f, 0.19509032201612825f,
        0.0f, -0.19509032201612825f, -0.3826834323650898f, -0.5555702330196022f,
        -0.7071067811865476f, -0.8314696123025452f, -0.9238795325112867f, -0.9807852804032304f };
    const float LS[16] = {
        0.0f, -0.19509032201612825f, -0.3826834323650898f, -0.5555702330196022f,
        -0.7071067811865476f, -0.8314696123025452f, -0.9238795325112867f, -0.9807852804032304f,
        -1.0f, -0.9807852804032304f, -0.9238795325112867f, -0.8314696123025452f,
        -0.7071067811865476f, -0.5555702330196022f, -0.3826834323650898f, -0.19509032201612825f };
    SWAPC(1,8) SWAPC(2,4) SWAPC(3,12) SWAPC(5,10) SWAPC(7,14) SWAPC(11,13)
    #pragma unroll
    for (int s = 1; s <= 4; s++) {
        const int half = 1 << (s - 1);
        #pragma unroll
        for (int k = 0; k < 8; k++) {
            int j  = k & (half - 1);
            int i1 = ((k >> (s - 1)) << s) + j;
            int i2 = i1 + half;
            int w  = j * (32 >> s);
            float cs = LC[w];
            float sn = (DIR < 0) ? LS[w] : -LS[w];
            float tr = xr[i2] * cs - xi[i2] * sn;
            float ti = xr[i2] * sn + xi[i2] * cs;
            xr[i2] = xr[i1] - tr; xi[i2] = xi[i1] - ti;
            xr[i1] += tr;         xi[i1] += ti;
        }
    }
}
#undef SWAPC

// ---- 8192-pt FFT (256 threads, 32 regs): passes 32 x 16 x 16 ---------------
// If WB: natural-order in RE/IM (+final sync). If !WB: pass-3 results in regs;
// map: xr[j2] <-> n = (tid&31) + 32*(tid>>5) + 512*j2, xr[16+j2] <-> n + 256.
template<int DIR, bool WB>
__device__ __forceinline__ void fft8k(float* RE, float* IM, float* xr, float* xi, int tid) {
    const float TW = (DIR < 0) ? -6.2831853071795864769f : 6.2831853071795864769f;
    fft32r<DIR>(xr, xi);
    {
        const float ang1 = TW * (float)tid * (1.0f / 8192.0f);
        RE[tid] = xr[0]; IM[tid] = xi[0];
        #pragma unroll
        for (int k1 = 1; k1 < 32; k1++) {
            float sn, cs;
            __sincosf(ang1 * (float)k1, &sn, &cs);
            RE[k1 * 272 + tid] = xr[k1] * cs - xi[k1] * sn;
            IM[k1 * 272 + tid] = xr[k1] * sn + xi[k1] * cs;
        }
    }
    __syncthreads();
    {
        int k1a = tid >> 4, m2 = tid & 15;
        int k1b = k1a + 16;
        #pragma unroll
        for (int m1 = 0; m1 < 16; m1++) {
            xr[m1]      = RE[k1a * 272 + m1 * 16 + m2];
            xi[m1]      = IM[k1a * 272 + m1 * 16 + m2];
            xr[16 + m1] = RE[k1b * 272 + m1 * 16 + m2];
            xi[16 + m1] = IM[k1b * 272 + m1 * 16 + m2];
        }
        __syncthreads();
        fft16r<DIR>(xr, xi);
        fft16r<DIR>(xr + 16, xi + 16);
        const float ang2 = TW * (float)m2 * (1.0f / 256.0f);
        int wba = k1a * 17 + m2, wbb = k1b * 17 + m2;
        RE[wba] = xr[0];  IM[wba] = xi[0];
        RE[wbb] = xr[16]; IM[wbb] = xi[16];
        #pragma unroll
        for (int j1 = 1; j1 < 16; j1++) {
            float sn, cs;
            __sincosf(ang2 * (float)j1, &sn, &cs);
            RE[j1 * 544 + wba] = xr[j1] * cs - xi[j1] * sn;
            IM[j1 * 544 + wba] = xr[j1] * sn + xi[j1] * cs;
            RE[j1 * 544 + wbb] = xr[16 + j1] * cs - xi[16 + j1] * sn;
            IM[j1 * 544 + wbb] = xr[16 + j1] * sn + xi[16 + j1] * cs;
        }
    }
    __syncthreads();
    {
        int k1 = tid & 31, j1a = tid >> 5, j1b = j1a + 8;
        #pragma unroll
        for (int m2 = 0; m2 < 16; m2++) {
            xr[m2]      = RE[j1a * 544 + k1 * 17 + m2];
            xi[m2]      = IM[j1a * 544 + k1 * 17 + m2];
            xr[16 + m2] = RE[j1b * 544 + k1 * 17 + m2];
            xi[16 + m2] = IM[j1b * 544 + k1 * 17 + m2];
        }
        if (WB) __syncthreads();
        fft16r<DIR>(xr, xi);
        fft16r<DIR>(xr + 16, xi + 16);
        if (WB) {
            #pragma unroll
            for (int j2 = 0; j2 < 16; j2++) {
                RE[k1 + 32 * j1a + 512 * j2] = xr[j2];
                IM[k1 + 32 * j1a + 512 * j2] = xi[j2];
                RE[k1 + 32 * j1b + 512 * j2] = xr[16 + j2];
                IM[k1 + 32 * j1b + 512 * j2] = xi[16 + j2];
            }
            __syncthreads();
        }
    }
}
#define CH_SMEM_FLOATS 8704

// ---------------- GEMM chunk-order helpers (shared-tile reuse) --------------
// Chunk order per kc: (sg1: A1*B0), (sg0: A0*B0), (sg2: A0*B1)
// A-slot = (2*kc + (j>=1)) % 3;  B-slot = (2*kc + (j==2)) % 3.

// ---------------- K1: up = u @ w_in + b_in (256 thr, 128x128, 3-ring) ------
#define UPA_STG 9216
#define UPB_STG 8704
#define UP_SMEM ((3 * UPA_STG + 3 * UPB_STG) * 2)   // 107520 B

__device__ __forceinline__ void up_loadA(__nv_bfloat16* dst, const __nv_bfloat16* Ap,
                                         int m0, int k0, int tid) {
    #pragma unroll
    for (int it = 0; it < 4; it++) {
        int id = tid + it * 256, r = id >> 3, cu = id & 7;
        cp16(cvta_s(dst + r * 72 + cu * 8), Ap + (size_t)(m0 + r) * Fq + k0 + cu * 8);
    }
}
__device__ __forceinline__ void up_loadB(__nv_bfloat16* dst, const __nv_bfloat16* Bp,
                                         int n0, int k0, int tid) {
    #pragma unroll
    for (int it = 0; it < 4; it++) {
        int id = tid + it * 256, r = id >> 4, cu = id & 15;
        cp16(cvta_s(dst + r * 136 + cu * 8), Bp + (size_t)(k0 + r) * IWq + n0 + cu * 8);
    }
}

__global__ void __launch_bounds__(256) gemm_up_tc(const float* __restrict__ bias) {
    extern __shared__ __align__(16) __nv_bfloat16 smp[];
    __nv_bfloat16* As = smp;
    __nv_bfloat16* Bs = smp + 3 * UPA_STG;
    const int m0 = blockIdx.y * 128, n0 = blockIdx.x * 128;
    const int tid = threadIdx.x, lane = tid & 31, wid = tid >> 5;
    const int wm = wid >> 2, wn = wid & 3;
    float acc[4][4][4] = {};

    up_loadA(As, g_ul, m0, 0, tid);
    up_loadB(Bs, g_wih, n0, 0, tid);
    cp_commit();
    up_loadA(As + UPA_STG, g_uh, m0, 0, tid);
    cp_commit();

    for (int c = 0; c < 36; c++) {
        if (c < 35) cp_wait1(); else cp_wait0();
        __syncthreads();
        int pf = c + 2;
        if (pf < 36) {
            int kcp = pf / 3, jp = pf % 3;
            if (jp <= 1)
                up_loadA(As + ((2 * kcp + (jp >= 1)) % 3) * UPA_STG,
                         (jp == 0) ? g_ul : g_uh, m0, kcp * 64, tid);
            if (jp != 1)
                up_loadB(Bs + ((2 * kcp + (jp == 2)) % 3) * UPB_STG,
                         (jp == 2) ? g_wil : g_wih, n0, kcp * 64, tid);
            cp_commit();
        }
        int kc = c / 3, j = c % 3;
        const __nv_bfloat16* Ab = As + ((2 * kc + (j >= 1)) % 3) * UPA_STG;
        const __nv_bfloat16* Bb = Bs + ((2 * kc + (j == 2)) % 3) * UPB_STG;
        #pragma unroll
        for (int ks = 0; ks < 4; ks++) {
            uint32_t a[4][4], bf[4][2];
            #pragma unroll
            for (int mi = 0; mi < 4; mi++) {
                const __nv_bfloat16* p = Ab + (wm * 64 + mi * 16 + (lane & 15)) * 72
                                            + ks * 16 + (lane >> 4) * 8;
                ldsm_x4(a[mi][0], a[mi][1], a[mi][2], a[mi][3], cvta_s(p));
            }
            #pragma unroll
            for (int pr = 0; pr < 2; pr++) {
                const __nv_bfloat16* p = Bb + (ks * 16 + (lane & 15)) * 136
                                            + wn * 32 + pr * 16 + (lane >> 4) * 8;
                ldsm_x4_t(bf[2*pr][0], bf[2*pr][1], bf[2*pr+1][0], bf[2*pr+1][1], cvta_s(p));
            }
            #pragma unroll
            for (int mi = 0; mi < 4; mi++)
                #pragma unroll
                for (int ni = 0; ni < 4; ni++)
                    mma_bf16(acc[mi][ni], a[mi], bf[ni]);
        }
    }
    #pragma unroll
    for (int mi = 0; mi < 4; mi++)
        #pragma unroll
        for (int ni = 0; ni < 4; ni++) {
            int row = m0 + wm * 64 + mi * 16 + (lane >> 2);
            int col = n0 + wn * 32 + ni * 8 + (lane & 3) * 2;
            float b0 = bias[col], b1 = bias[col + 1];
            *(float2*)&g_up[(size_t)row * IWq + col] =
                make_float2(acc[mi][ni][0] + b0, acc[mi][ni][1] + b1);
            *(float2*)&g_up[(size_t)(row + 8) * IWq + col] =
                make_float2(acc[mi][ni][2] + b0, acc[mi][ni][3] + b1);
        }
}

// ---------------- K2: depthwise conv + split + gate (float4 loads) ---------
__global__ void __launch_bounds__(256) conv_gate(const float* __restrict__ convk,
                                                 const float* __restrict__ convb) {
    __shared__ float s_in[34 * 4 * 32];
    __shared__ float s_out[3][32][33];
    const int f0 = blockIdx.x * 32, t0 = blockIdx.y * 32, b = blockIdx.z;
    const int tid = threadIdx.x, tx = tid & 31, ty = tid >> 5;

    for (int q = tid; q < 136 * 8; q += 256) {
        int row = q >> 3, w = q & 7;
        int tt = row >> 2, c4 = row & 3;
        int t = t0 - 2 + tt;
        float4 v = make_float4(0.f, 0.f, 0.f, 0.f);
        if (t >= 0)
            v = *(const float4*)&g_up[(size_t)(b * Lq + t) * IWq + c4 * Fq + f0 + w * 4];
        *(float4*)&s_in[row * 32 + w * 4] = v;
    }
    float kk[4][3], cb[4];
    #pragma unroll
    for (int c4 = 0; c4 < 4; c4++) {
        int c = c4 * Fq + f0 + tx;
        kk[c4][0] = convk[c]; kk[c4][1] = convk[IWq + c]; kk[c4][2] = convk[2 * IWq + c];
        cb[c4] = convb[c];
    }
    __syncthreads();
    #pragma unroll
    for (int q = 0; q < 4; q++) {
        int ts = ty + 8 * q;
        float o[4];
        #pragma unroll
        for (int c4 = 0; c4 < 4; c4++)
            o[c4] = cb[c4]
                  + kk[c4][2] * s_in[((ts + 2) * 4 + c4) * 32 + tx]
                  + kk[c4][1] * s_in[((ts + 1) * 4 + c4) * 32 + tx]
                  + kk[c4][0] * s_in[((ts    ) * 4 + c4) * 32 + tx];
        s_out[0][tx][ts] = o[3] * o[0];
        s_out[1][tx][ts] = o[1];
        s_out[2][tx][ts] = o[2];
    }
    __syncthreads();
    float* dst[3] = { g_v, g_x1, g_x2 };
    #pragma unroll
    for (int jn = 0; jn < 3; jn++)
        #pragma unroll
        for (int qq = 0; qq < 4; qq++) {
            int fr = ty + 8 * qq;
            dst[jn][(size_t)(b * Fq + f0 + fr) * Lq + t0 + tx] = s_out[jn][fr][tx];
        }
}

// ---------------- K3: per-(o,f) 8192-pt real-packed FFT of h ---------------
__global__ void __launch_bounds__(256) hfft_kernel() {
    extern __shared__ float sm[];
    float* RE = sm;
    float* IM = sm + CH_SMEM_FLOATS;
    const int idx = blockIdx.x;           // o * Fq + f
    const int tid = threadIdx.x;
    const float* hsrc = g_ht + (size_t)idx * Lq;
    float xr[32], xi[32];
    #pragma unroll
    for (int n1 = 0; n1 < 32; n1++) {
        if (n1 < 16) {
            float2 hh = *(const float2*)&hsrc[2 * (n1 * 256 + tid)];
            xr[n1] = hh.x; xi[n1] = hh.y;
        } else { xr[n1] = 0.0f; xi[n1] = 0.0f; }
    }
    fft8k<-1, true>(RE, IM, xr, xi, tid);     // Z natural-order in RE/IM
    float2* H = g_H + (size_t)idx * HSTR;
    #pragma unroll
    for (int n1 = 0; n1 < 32; n1++) {
        int k   = n1 * 256 + tid;
        int kks = (8192 - k) & 8191;
        float zr = RE[k],   zi = IM[k];
        float wr = RE[kks], wi = IM[kks];
        float zer = 0.5f * (zr + wr), zei = 0.5f * (zi - wi);
        float zor = 0.5f * (zi + wi), zoi = 0.5f * (wr - zr);
        float sn, cs;
        __sincosf(-6.2831853071795864769f * (float)k * (1.0f / 16384.0f), &sn, &cs);
        H[k] = make_float2(zer + cs * zor - sn * zoi,
                           zei + cs * zoi + sn * zor);
    }
    if (tid == 0)
        H[8192] = make_float2(RE[0] - IM[0], 0.0f);   // V[8192] = ReZ0 - ImZ0
}

// ---------------- K4: per-(b, f) chain via 8192-pt real-packed FFT ---------
__global__ void __launch_bounds__(256) chain_kernel(const float* __restrict__ bias) {
    extern __shared__ float sm[];
    float* RE = sm;
    float* IM = sm + CH_SMEM_FLOATS;
    const int idx = blockIdx.x;           // b * Fq + f
    const int b = idx / Fq, f = idx % Fq;
    const int tid = threadIdx.x;
    const size_t base = ((size_t)b * Fq + f) * Lq;
    const float inv = 1.0f / 8192.0f;
    float xr[32], xi[32];

    #pragma unroll 1
    for (int o = 0; o < 2; o++) {
        #pragma unroll
        for (int n1 = 0; n1 < 32; n1++) {
            if (n1 < 16) {
                float2 vv = *(const float2*)&g_v[base + 2 * (n1 * 256 + tid)];
                xr[n1] = vv.x; xi[n1] = vv.y;
            } else { xr[n1] = 0.0f; xi[n1] = 0.0f; }
        }
        fft8k<-1, true>(RE, IM, xr, xi, tid);

        const float2* Hf = g_H + ((size_t)o * Fq + f) * HSTR;
        #pragma unroll
        for (int n1 = 0; n1 < 32; n1++) {
            int k   = n1 * 256 + tid;
            int kks = (8192 - k) & 8191;
            int kp  = 8192 - k;
            float zr = RE[k],   zi = IM[k];
            float wr = RE[kks], wi = IM[kks];
            float zer = 0.5f * (zr + wr), zei = 0.5f * (zi - wi);
            float zor = 0.5f * (zi + wi), zoi = 0.5f * (wr - zr);
            float sn, cs;
            __sincosf(-6.2831853071795864769f * (float)k * (1.0f / 16384.0f), &sn, &cs);
            float vkr = zer + cs * zor - sn * zoi;
            float vki = zei + cs * zoi + sn * zor;
            float vpr = zer - cs * zor + sn * zoi;
            float vpi = -zei + cs * zoi + sn * zor;
            float2 hk = Hf[k], hp = Hf[kp];
            float ykr = vkr * hk.x - vki * hk.y, yki = vkr * hk.y + vki * hk.x;
            float ypr = vpr * hp.x - vpi * hp.y, ypi = vpr * hp.y + vpi * hp.x;
            float er  = 0.5f * (ykr + ypr), ei  = 0.5f * (yki - ypi);
            float ocr = 0.5f * (ykr - ypr), oci = 0.5f * (yki + ypi);
            float orr = cs * ocr + sn * oci;
            float ori = cs * oci - sn * ocr;
            xr[n1] = er - ori;
            xi[n1] = ei + orr;
        }
        __syncthreads();
        fft8k<1, false>(RE, IM, xr, xi, tid);

        const float bo = bias[o * Fq + f];
        const float* X = (o == 0 ? g_x1 : g_x2) + base;
        const int k1 = tid & 31, j1a = tid >> 5;
        if (o == 0) {
            #pragma unroll
            for (int j2 = 0; j2 < 8; j2++) {
                int n  = k1 + 32 * j1a + 512 * j2;
                int n2 = n + 256;
                float2 vo = *(const float2*)&g_v[base + 2 * n];
                float2 xg = *(const float2*)&X[2 * n];
                float2 w;
                w.x = (xr[j2] * inv + vo.x * bo) * xg.x;
                w.y = (xi[j2] * inv + vo.y * bo) * xg.y;
                *(float2*)&g_v[base + 2 * n] = w;
                float2 vo2 = *(const float2*)&g_v[base + 2 * n2];
                float2 xg2 = *(const float2*)&X[2 * n2];
                float2 w2;
                w2.x = (xr[16 + j2] * inv + vo2.x * bo) * xg2.x;
                w2.y = (xi[16 + j2] * inv + vo2.y * bo) * xg2.y;
                *(float2*)&g_v[base + 2 * n2] = w2;
            }
        } else {
            #pragma unroll
            for (int j2 = 0; j2 < 8; j2++) {
                int n  = k1 + 32 * j1a + 512 * j2;
                int n2 = n + 256;
                float2 vo = *(const float2*)&g_v[base + 2 * n];
                float2 xg = *(const float2*)&X[2 * n];
                float y0 = (xr[j2] * inv + vo.x * bo) * xg.x;
                float y1 = (xi[j2] * inv + vo.y * bo) * xg.y;
                __nv_bfloat16 h0 = __float2bfloat16(y0);
                __nv_bfloat16 h1 = __float2bfloat16(y1);
                g_vh[base + 2 * n]     = h0;
                g_vh[base + 2 * n + 1] = h1;
                g_vl[base + 2 * n]     = __float2bfloat16(y0 - __bfloat162float(h0));
                g_vl[base + 2 * n + 1] = __float2bfloat16(y1 - __bfloat162float(h1));
                float2 vo2 = *(const float2*)&g_v[base + 2 * n2];
                float2 xg2 = *(const float2*)&X[2 * n2];
                float y2 = (xr[16 + j2] * inv + vo2.x * bo) * xg2.x;
                float y3 = (xi[16 + j2] * inv + vo2.y * bo) * xg2.y;
                __nv_bfloat16 h2 = __float2bfloat16(y2);
                __nv_bfloat16 h3 = __float2bfloat16(y3);
                g_vh[base + 2 * n2]     = h2;
                g_vh[base + 2 * n2 + 1] = h3;
                g_vl[base + 2 * n2]     = __float2bfloat16(y2 - __bfloat162float(h2));
                g_vl[base + 2 * n2 + 1] = __float2bfloat16(y3 - __bfloat162float(h3));
            }
        }
        __syncthreads();
    }
}

// ---------------- K5: out = v2 @ w_out + b_out (256 thr, 128x128, 3-ring) --
#define OTA_STG 8704
#define OTB_STG 8704
#define OT_SMEM ((3 * OTA_STG + 3 * OTB_STG) * 2)   // 104448 B

__device__ __forceinline__ void out_loadA(__nv_bfloat16* dst, const __nv_bfloat16* Ap,
                                          int t0, int k0, int tid) {
    #pragma unroll
    for (int it = 0; it < 4; it++) {
        int id = tid + it * 256, r = id >> 4, cu = id & 15;
        cp16(cvta_s(dst + r * 136 + cu * 8), Ap + (size_t)(k0 + r) * Lq + t0 + cu * 8);
    }
}
__device__ __forceinline__ void out_loadB(__nv_bfloat16* dst, const __nv_bfloat16* Bp,
                                          int n0, int k0, int tid) {
    #pragma unroll
    for (int it = 0; it < 4; it++) {
        int id = tid + it * 256, r = id >> 4, cu = id & 15;
        cp16(cvta_s(dst + r * 136 + cu * 8), Bp + (size_t)(k0 + r) * Fq + n0 + cu * 8);
    }
}

__global__ void __launch_bounds__(256) gemm_out_tc(const float* __restrict__ bias,
                                                   float* __restrict__ out) {
    extern __shared__ __align__(16) __nv_bfloat16 smp[];
    __nv_bfloat16* As = smp;
    __nv_bfloat16* Bs = smp + 3 * OTA_STG;
    const int m0 = blockIdx.y * 128, n0 = blockIdx.x * 128;
    const int b = m0 / Lq, t0 = m0 % Lq;
    const int tid = threadIdx.x, lane = tid & 31, wid = tid >> 5;
    const int wm = wid >> 2, wn = wid & 3;
    float acc[4][4][4] = {};

    const size_t abase = (size_t)b * Fq * Lq;
    const __nv_bfloat16* Avh = g_vh + abase;
    const __nv_bfloat16* Avl = g_vl + abase;

    out_loadA(As, Avl, t0, 0, tid);
    out_loadB(Bs, g_woh, n0, 0, tid);
    cp_commit();
    out_loadA(As + OTA_STG, Avh, t0, 0, tid);
    cp_commit();

    for (int c = 0; c < 36; c++) {
        if (c < 35) cp_wait1(); else cp_wait0();
        __syncthreads();
        int pf = c + 2;
        if (pf < 36) {
            int kcp = pf / 3, jp = pf % 3;
            if (jp <= 1)
                out_loadA(As + ((2 * kcp + (jp >= 1)) % 3) * OTA_STG,
                          (jp == 0) ? Avl : Avh, t0, kcp * 64, tid);
            if (jp != 1)
                out_loadB(Bs + ((2 * kcp + (jp == 2)) % 3) * OTB_STG,
                          (jp == 2) ? g_wol : g_woh, n0, kcp * 64, tid);
            cp_commit();
        }
        int kc = c / 3, j = c % 3;
        const __nv_bfloat16* Ab = As + ((2 * kc + (j >= 1)) % 3) * OTA_STG;
        const __nv_bfloat16* Bb = Bs + ((2 * kc + (j == 2)) % 3) * OTB_STG;
        #pragma unroll
        for (int ks = 0; ks < 4; ks++) {
            uint32_t a[4][4], bf[4][2];
            #pragma unroll
            for (int mi = 0; mi < 4; mi++) {
                int krow = ks * 16 + ((lane >> 4) ? 8 : 0) + (lane & 7);
                int mcol = wm * 64 + mi * 16 + ((lane >> 3) & 1) * 8;
                const __nv_bfloat16* p = Ab + krow * 136 + mcol;
                ldsm_x4_t(a[mi][0], a[mi][1], a[mi][2], a[mi][3], cvta_s(p));
            }
            #pragma unroll
            for (int pr = 0; pr < 2; pr++) {
                const __nv_bfloat16* p = Bb + (ks * 16 + (lane & 15)) * 136
                                            + wn * 32 + pr * 16 + (lane >> 4) * 8;
                ldsm_x4_t(bf[2*pr][0], bf[2*pr][1], bf[2*pr+1][0], bf[2*pr+1][1], cvta_s(p));
            }
            #pragma unroll
            for (int mi = 0; mi < 4; mi++)
                #pragma unroll
                for (int ni = 0; ni < 4; ni++)
                    mma_bf16(acc[mi][ni], a[mi], bf[ni]);
        }
    }
    #pragma unroll
    for (int mi = 0; mi < 4; mi++)
        #pragma unroll
        for (int ni = 0; ni < 4; ni++) {
            int row = m0 + wm * 64 + mi * 16 + (lane >> 2);
            int col = n0 + wn * 32 + ni * 8 + (lane & 3) * 2;
            float b0 = bias[col], b1 = bias[col + 1];
            *(float2*)&out[(size_t)row * Fq + col] =
                make_float2(acc[mi][ni][0] + b0, acc[mi][ni][1] + b1);
            *(float2*)&out[(size_t)(row + 8) * Fq + col] =
                make_float2(acc[mi][ni][2] + b0, acc[mi][ni][3] + b1);
        }
}

// ---------------- launch -----------------------------------------------------
extern "C" void kernel_launch(void* const* d_in, const int* in_sizes, int n_in,
                              void* d_out, int out_size) {
    const float* u      = (const float*)d_in[0];
    const float* h      = (const float*)d_in[1];
    const float* bias   = (const float*)d_in[2];
    const float* w_in   = (const float*)d_in[3];
    const float* b_in   = (const float*)d_in[4];
    const float* conv_k = (const float*)d_in[5];
    const float* conv_b = (const float*)d_in[6];
    const float* w_out  = (const float*)d_in[7];
    const float* b_out  = (const float*)d_in[8];
    float* out = (float*)d_out;

    const int ch_smem = CH_SMEM_FLOATS * 2 * sizeof(float);    // 69632
    cudaFuncSetAttribute(hfft_kernel,  cudaFuncAttributeMaxDynamicSharedMemorySize, ch_smem);
    cudaFuncSetAttribute(chain_kernel, cudaFuncAttributeMaxDynamicSharedMemorySize, ch_smem);
    cudaFuncSetAttribute(gemm_up_tc,   cudaFuncAttributeMaxDynamicSharedMemorySize, UP_SMEM);
    cudaFuncSetAttribute(gemm_out_tc,  cudaFuncAttributeMaxDynamicSharedMemorySize, OT_SMEM);

    prep_kernel<<<NB_U + NB_WI + NB_WO + NB_T, 256>>>(u, w_in, w_out, h);
    hfft_kernel<<<2 * Fq, 256, ch_smem>>>();
    gemm_up_tc<<<dim3(IWq / 128, Mq / 128), 256, UP_SMEM>>>(b_in);
    conv_gate<<<dim3(Fq / 32, Lq / 32, Bq), 256>>>(conv_k, conv_b);
    chain_kernel<<<Bq * Fq, 256, ch_smem>>>(bias);
    gemm_out_tc<<<dim3(Fq / 128, Mq / 128), 256, OT_SMEM>>>(b_out, out);
}